// round 5
// baseline (speedup 1.0000x reference)
#include <cuda_runtime.h>

#define BB   8
#define SS   2048
#define DD   1024
#define CHK  64
#define NCHK (SS / CHK)
#define LRc  0.01f
#define LAM  (2.0f * 0.01f / 1024.0f)
#define GSC  (2.0f / 1024.0f)

// ---------------- static device scratch ----------------
__device__ float g_K [BB * SS * DD];
__device__ float g_Q [BB * SS * DD];
__device__ float g_U [BB * SS * DD];
__device__ float g_M [BB * DD * DD];
__device__ float g_s [BB * DD];
__device__ float g_G [BB * CHK * DD];
__device__ float g_Up[BB * CHK * DD];
__device__ float g_Skk[BB * NCHK * CHK * CHK];
__device__ float g_Aqk[BB * NCHK * CHK * CHK];
__device__ float g_Ti [BB * NCHK * CHK * CHK];
__device__ float g_E [DD * DD];
__device__ float g_F [DD * DD];

// =====================================================================
// NT GEMM: C[m,n] = alpha*(sum_k A[m,k]*B[n,k] + bias[n]); 64x64 tile BK=32
// =====================================================================
__global__ void __launch_bounds__(256) gemm_nt(
    const float* __restrict__ A, int lda,
    const float* __restrict__ Bm, int ldb,
    float* __restrict__ C, int ldc,
    const float* __restrict__ bias, float alpha, int K)
{
    int m0 = blockIdx.y << 6, n0 = blockIdx.x << 6;
    __shared__ float As[32][68];
    __shared__ float Bs[32][68];
    int tid = threadIdx.x;
    int tx = tid & 15, ty = tid >> 4;
    int lr = tid >> 3, lc = (tid & 7) << 2;
    const float* Ap = A  + (long)(m0 + lr) * lda + lc;
    const float* Bp = Bm + (long)(n0 + lr) * ldb + lc;
    float acc[4][4] = {};
    for (int kb = 0; kb < K; kb += 32) {
        float4 a0 = *(const float4*)(Ap + kb);
        float4 a1 = *(const float4*)(Ap + kb + (long)32 * lda);
        float4 b0v = *(const float4*)(Bp + kb);
        float4 b1v = *(const float4*)(Bp + kb + (long)32 * ldb);
        __syncthreads();
        As[lc+0][lr]=a0.x; As[lc+1][lr]=a0.y; As[lc+2][lr]=a0.z; As[lc+3][lr]=a0.w;
        As[lc+0][lr+32]=a1.x; As[lc+1][lr+32]=a1.y; As[lc+2][lr+32]=a1.z; As[lc+3][lr+32]=a1.w;
        Bs[lc+0][lr]=b0v.x; Bs[lc+1][lr]=b0v.y; Bs[lc+2][lr]=b0v.z; Bs[lc+3][lr]=b0v.w;
        Bs[lc+0][lr+32]=b1v.x; Bs[lc+1][lr+32]=b1v.y; Bs[lc+2][lr+32]=b1v.z; Bs[lc+3][lr+32]=b1v.w;
        __syncthreads();
#pragma unroll
        for (int kk = 0; kk < 32; kk++) {
            float4 av = *(const float4*)(&As[kk][ty << 2]);
            float4 bv = *(const float4*)(&Bs[kk][tx << 2]);
            acc[0][0]+=av.x*bv.x; acc[0][1]+=av.x*bv.y; acc[0][2]+=av.x*bv.z; acc[0][3]+=av.x*bv.w;
            acc[1][0]+=av.y*bv.x; acc[1][1]+=av.y*bv.y; acc[1][2]+=av.y*bv.z; acc[1][3]+=av.y*bv.w;
            acc[2][0]+=av.z*bv.x; acc[2][1]+=av.z*bv.y; acc[2][2]+=av.z*bv.z; acc[2][3]+=av.z*bv.w;
            acc[3][0]+=av.w*bv.x; acc[3][1]+=av.w*bv.y; acc[3][2]+=av.w*bv.z; acc[3][3]+=av.w*bv.w;
        }
    }
#pragma unroll
    for (int i = 0; i < 4; i++) {
        long row = m0 + (ty << 2) + i;
#pragma unroll
        for (int j = 0; j < 4; j++) {
            int col = n0 + (tx << 2) + j;
            float v = acc[i][j];
            if (bias) v += bias[col];
            C[row * ldc + col] = alpha * v;
        }
    }
}

// =====================================================================
// NN GEMM: C = alpha*A@B + beta*Cin   (square 1024 use only)
// =====================================================================
__global__ void __launch_bounds__(256) gemm_nn(
    const float* __restrict__ A, int lda,
    const float* __restrict__ Bm, int ldb,
    float* __restrict__ C, int ldc,
    const float* __restrict__ Cin, float beta, float alpha, int K)
{
    int m0 = blockIdx.y << 6, n0 = blockIdx.x << 6;
    __shared__ float As[32][68];
    __shared__ float Bs[32][68];
    int tid = threadIdx.x;
    int tx = tid & 15, ty = tid >> 4;
    int lr = tid >> 3, lc = (tid & 7) << 2;
    int bkr = tid >> 4, bc = (tid & 15) << 2;
    const float* Ap = A  + (long)(m0 + lr) * lda + lc;
    const float* Bp = Bm + (long)bkr * ldb + n0 + bc;
    float acc[4][4] = {};
    for (int kb = 0; kb < K; kb += 32) {
        float4 a0 = *(const float4*)(Ap + kb);
        float4 a1 = *(const float4*)(Ap + kb + (long)32 * lda);
        float4 bv0 = *(const float4*)(Bp + (long)kb * ldb);
        float4 bv1 = *(const float4*)(Bp + (long)(kb + 16) * ldb);
        __syncthreads();
        As[lc+0][lr]=a0.x; As[lc+1][lr]=a0.y; As[lc+2][lr]=a0.z; As[lc+3][lr]=a0.w;
        As[lc+0][lr+32]=a1.x; As[lc+1][lr+32]=a1.y; As[lc+2][lr+32]=a1.z; As[lc+3][lr+32]=a1.w;
        *(float4*)(&Bs[bkr][bc])      = bv0;
        *(float4*)(&Bs[bkr + 16][bc]) = bv1;
        __syncthreads();
#pragma unroll
        for (int kk = 0; kk < 32; kk++) {
            float4 av = *(const float4*)(&As[kk][ty << 2]);
            float4 bv = *(const float4*)(&Bs[kk][tx << 2]);
            acc[0][0]+=av.x*bv.x; acc[0][1]+=av.x*bv.y; acc[0][2]+=av.x*bv.z; acc[0][3]+=av.x*bv.w;
            acc[1][0]+=av.y*bv.x; acc[1][1]+=av.y*bv.y; acc[1][2]+=av.y*bv.z; acc[1][3]+=av.y*bv.w;
            acc[2][0]+=av.z*bv.x; acc[2][1]+=av.z*bv.y; acc[2][2]+=av.z*bv.z; acc[2][3]+=av.z*bv.w;
            acc[3][0]+=av.w*bv.x; acc[3][1]+=av.w*bv.y; acc[3][2]+=av.w*bv.z; acc[3][3]+=av.w*bv.w;
        }
    }
#pragma unroll
    for (int i = 0; i < 4; i++) {
        long row = m0 + (ty << 2) + i;
#pragma unroll
        for (int j = 0; j < 4; j++) {
            int col = n0 + (tx << 2) + j;
            float v = alpha * acc[i][j];
            if (beta != 0.f) v += beta * Cin[row * ldc + col];
            C[row * ldc + col] = v;
        }
    }
}

// =====================================================================
// Gram pairs per (batch,chunk): Skk = Kc@Kc^T, Aqk = Qc@Kc^T (64x64, K=1024)
// grid: x=NCHK, y=2, z=BB
// =====================================================================
__global__ void __launch_bounds__(256) pair_kernel(
    const float* __restrict__ Km, const float* __restrict__ Qm,
    float* __restrict__ Skk, float* __restrict__ Aqk)
{
    int c = blockIdx.x, b = blockIdx.z;
    long rowoff = ((long)b * SS + (long)c * CHK) * DD;
    const float* A = (blockIdx.y == 0) ? (Km + rowoff) : (Qm + rowoff);
    const float* Bm = Km + rowoff;
    float* C = ((blockIdx.y == 0) ? Skk : Aqk) + ((long)b * NCHK + c) * 4096;
    __shared__ float As[32][68];
    __shared__ float Bs[32][68];
    int tid = threadIdx.x;
    int tx = tid & 15, ty = tid >> 4;
    int lr = tid >> 3, lc = (tid & 7) << 2;
    const float* Ap = A  + (long)lr * DD + lc;
    const float* Bp = Bm + (long)lr * DD + lc;
    float acc[4][4] = {};
    for (int kb = 0; kb < DD; kb += 32) {
        float4 a0 = *(const float4*)(Ap + kb);
        float4 a1 = *(const float4*)(Ap + kb + (long)32 * DD);
        float4 b0v = *(const float4*)(Bp + kb);
        float4 b1v = *(const float4*)(Bp + kb + (long)32 * DD);
        __syncthreads();
        As[lc+0][lr]=a0.x; As[lc+1][lr]=a0.y; As[lc+2][lr]=a0.z; As[lc+3][lr]=a0.w;
        As[lc+0][lr+32]=a1.x; As[lc+1][lr+32]=a1.y; As[lc+2][lr+32]=a1.z; As[lc+3][lr+32]=a1.w;
        Bs[lc+0][lr]=b0v.x; Bs[lc+1][lr]=b0v.y; Bs[lc+2][lr]=b0v.z; Bs[lc+3][lr]=b0v.w;
        Bs[lc+0][lr+32]=b1v.x; Bs[lc+1][lr+32]=b1v.y; Bs[lc+2][lr+32]=b1v.z; Bs[lc+3][lr+32]=b1v.w;
        __syncthreads();
#pragma unroll
        for (int kk = 0; kk < 32; kk++) {
            float4 av = *(const float4*)(&As[kk][ty << 2]);
            float4 bv = *(const float4*)(&Bs[kk][tx << 2]);
            acc[0][0]+=av.x*bv.x; acc[0][1]+=av.x*bv.y; acc[0][2]+=av.x*bv.z; acc[0][3]+=av.x*bv.w;
            acc[1][0]+=av.y*bv.x; acc[1][1]+=av.y*bv.y; acc[1][2]+=av.y*bv.z; acc[1][3]+=av.y*bv.w;
            acc[2][0]+=av.z*bv.x; acc[2][1]+=av.z*bv.y; acc[2][2]+=av.z*bv.z; acc[2][3]+=av.z*bv.w;
            acc[3][0]+=av.w*bv.x; acc[3][1]+=av.w*bv.y; acc[3][2]+=av.w*bv.z; acc[3][3]+=av.w*bv.w;
        }
    }
#pragma unroll
    for (int i = 0; i < 4; i++)
#pragma unroll
        for (int j = 0; j < 4; j++)
            C[((ty << 2) + i) * 64 + (tx << 2) + j] = acc[i][j];
}

// =====================================================================
// Tinv = (I + LAM*strict_lower(Skk+1))^{-1}; column-private fwd subst.
// =====================================================================
__global__ void tinv_kernel(const float* __restrict__ Skk, float* __restrict__ Tinv)
{
    long z = blockIdx.x;
    const float* Ain = Skk + z * 4096;
    float* T = Tinv + z * 4096;
    __shared__ float A[64][64];
    __shared__ float Ts[64][64];
    int j = threadIdx.x;
    for (int t = 0; t < 64; t++) A[t][j] = Ain[t * 64 + j] + 1.0f;
    __syncthreads();
    for (int t = 0; t < 64; t++) {
        float v;
        if (t < j) v = 0.f;
        else if (t == j) v = 1.f;
        else {
            float ssum = 0.f;
            for (int i = j; i < t; i++) ssum += A[t][i] * Ts[i][j];
            v = -LAM * ssum;
        }
        Ts[t][j] = v;
    }
    __syncthreads();
    for (int t = 0; t < 64; t++) T[t * 64 + j] = Ts[t][j];
}

// =====================================================================
// Cross per chunk: y=0: Up = U_c - LAM*(Kc@M^T + s); y=1: out_c -= LR*(Qc@M^T + s)
// grid (16, 2, 8)
// =====================================================================
__global__ void __launch_bounds__(256) cross_kernel(int chunk,
    const float* __restrict__ Km, const float* __restrict__ Qm,
    const float* __restrict__ U, const float* __restrict__ Mm,
    const float* __restrict__ s, float* __restrict__ Up, float* __restrict__ out)
{
    int b = blockIdx.z;
    long rowoff = ((long)b * SS + (long)chunk * CHK) * DD;
    const float* A; const float* Cin; float* C; float alpha;
    if (blockIdx.y == 0) { A = Km + rowoff; Cin = U + rowoff;   C = Up + (long)b * CHK * DD; alpha = -LAM; }
    else                 { A = Qm + rowoff; Cin = out + rowoff; C = out + rowoff;            alpha = -LRc; }
    const float* Bm = Mm + (long)b * DD * DD;
    const float* bi = s  + (long)b * DD;
    int n0 = blockIdx.x << 6;
    __shared__ float As[32][68];
    __shared__ float Bs[32][68];
    int tid = threadIdx.x;
    int tx = tid & 15, ty = tid >> 4;
    int lr = tid >> 3, lc = (tid & 7) << 2;
    const float* Ap = A  + (long)lr * DD + lc;
    const float* Bp = Bm + (long)(n0 + lr) * DD + lc;
    float acc[4][4] = {};
    for (int kb = 0; kb < DD; kb += 32) {
        float4 a0 = *(const float4*)(Ap + kb);
        float4 a1 = *(const float4*)(Ap + kb + (long)32 * DD);
        float4 b0v = *(const float4*)(Bp + kb);
        float4 b1v = *(const float4*)(Bp + kb + (long)32 * DD);
        __syncthreads();
        As[lc+0][lr]=a0.x; As[lc+1][lr]=a0.y; As[lc+2][lr]=a0.z; As[lc+3][lr]=a0.w;
        As[lc+0][lr+32]=a1.x; As[lc+1][lr+32]=a1.y; As[lc+2][lr+32]=a1.z; As[lc+3][lr+32]=a1.w;
        Bs[lc+0][lr]=b0v.x; Bs[lc+1][lr]=b0v.y; Bs[lc+2][lr]=b0v.z; Bs[lc+3][lr]=b0v.w;
        Bs[lc+0][lr+32]=b1v.x; Bs[lc+1][lr+32]=b1v.y; Bs[lc+2][lr+32]=b1v.z; Bs[lc+3][lr+32]=b1v.w;
        __syncthreads();
#pragma unroll
        for (int kk = 0; kk < 32; kk++) {
            float4 av = *(const float4*)(&As[kk][ty << 2]);
            float4 bv = *(const float4*)(&Bs[kk][tx << 2]);
            acc[0][0]+=av.x*bv.x; acc[0][1]+=av.x*bv.y; acc[0][2]+=av.x*bv.z; acc[0][3]+=av.x*bv.w;
            acc[1][0]+=av.y*bv.x; acc[1][1]+=av.y*bv.y; acc[1][2]+=av.y*bv.z; acc[1][3]+=av.y*bv.w;
            acc[2][0]+=av.z*bv.x; acc[2][1]+=av.z*bv.y; acc[2][2]+=av.z*bv.z; acc[2][3]+=av.z*bv.w;
            acc[3][0]+=av.w*bv.x; acc[3][1]+=av.w*bv.y; acc[3][2]+=av.w*bv.z; acc[3][3]+=av.w*bv.w;
        }
    }
#pragma unroll
    for (int i = 0; i < 4; i++) {
        long row = (ty << 2) + i;
#pragma unroll
        for (int j = 0; j < 4; j++) {
            int col = n0 + (tx << 2) + j;
            C[row * DD + col] = Cin[row * DD + col] + alpha * (acc[i][j] + bi[col]);
        }
    }
}

// =====================================================================
// Solve per chunk: G = Tinv@Up (64x1024), s += colsum(G). grid (16, 8)
// =====================================================================
__global__ void __launch_bounds__(256) solve_kernel(int chunk,
    const float* __restrict__ Tinv, const float* __restrict__ Up,
    float* __restrict__ G, float* __restrict__ s)
{
    int b = blockIdx.y;
    int n0 = blockIdx.x << 6;
    const float* T = Tinv + ((long)b * NCHK + chunk) * 4096;
    const float* U = Up + (long)b * CHK * DD;
    float* Gb = G + (long)b * CHK * DD;
    __shared__ float Tt[64 * 65];
    __shared__ float Bs[64 * 64];
    int tid = threadIdx.x, tx = tid & 15, ty = tid >> 4;
    for (int i = tid; i < 4096; i += 256) { int t = i >> 6, jj = i & 63; Tt[jj * 65 + t] = T[i]; }
    for (int i = tid; i < 4096; i += 256) { int r = i >> 6, c = i & 63; Bs[(r << 6) + c] = U[(long)r * DD + n0 + c]; }
    __syncthreads();
    float acc[4][4] = {};
#pragma unroll 16
    for (int kk = 0; kk < 64; kk++) {
        const float* ap = &Tt[kk * 65 + (ty << 2)];
        float a0 = ap[0], a1 = ap[1], a2 = ap[2], a3 = ap[3];
        float4 bv = *(const float4*)(&Bs[(kk << 6) + (tx << 2)]);
        acc[0][0]+=a0*bv.x; acc[0][1]+=a0*bv.y; acc[0][2]+=a0*bv.z; acc[0][3]+=a0*bv.w;
        acc[1][0]+=a1*bv.x; acc[1][1]+=a1*bv.y; acc[1][2]+=a1*bv.z; acc[1][3]+=a1*bv.w;
        acc[2][0]+=a2*bv.x; acc[2][1]+=a2*bv.y; acc[2][2]+=a2*bv.z; acc[2][3]+=a2*bv.w;
        acc[3][0]+=a3*bv.x; acc[3][1]+=a3*bv.y; acc[3][2]+=a3*bv.z; acc[3][3]+=a3*bv.w;
    }
#pragma unroll
    for (int i = 0; i < 4; i++) {
        long row = (ty << 2) + i;
#pragma unroll
        for (int j = 0; j < 4; j++)
            Gb[row * DD + n0 + (tx << 2) + j] = acc[i][j];
    }
    __syncthreads();
    float* red = Tt;
#pragma unroll
    for (int j = 0; j < 4; j++)
        red[ty * 64 + (tx << 2) + j] = acc[0][j] + acc[1][j] + acc[2][j] + acc[3][j];
    __syncthreads();
    if (tid < 64) {
        float tot = 0.f;
#pragma unroll
        for (int r = 0; r < 16; r++) tot += red[r * 64 + tid];
        s[(long)b * DD + n0 + tid] += tot;
    }
}

// =====================================================================
// Z2 per chunk: x<16: out_c -= LR * (mask(Aqk+1)) @ G ; x>=16: M += G^T @ Kc
// grid (16+256, 8)
// =====================================================================
__global__ void __launch_bounds__(256) z2_kernel(int chunk,
    const float* __restrict__ Aqk, const float* __restrict__ G,
    const float* __restrict__ Kmat, float* __restrict__ out, float* __restrict__ Mm)
{
    int b = blockIdx.y;
    int x = blockIdx.x;
    __shared__ float SA[64 * 65];
    __shared__ float SB[64 * 64];
    int tid = threadIdx.x, tx = tid & 15, ty = tid >> 4;
    float acc[4][4] = {};
    const float* Gb = G + (long)b * CHK * DD;

    if (x < 16) {
        int n0 = x << 6;
        const float* Aq = Aqk + ((long)b * NCHK + chunk) * 4096;
        for (int i = tid; i < 4096; i += 256) {
            int t = i >> 6, c = i & 63;
            SA[c * 65 + t] = (c <= t) ? (Aq[i] + 1.0f) : 0.0f;
        }
        for (int i = tid; i < 4096; i += 256) {
            int r = i >> 6, c = i & 63;
            SB[(r << 6) + c] = Gb[(long)r * DD + n0 + c];
        }
        __syncthreads();
#pragma unroll 16
        for (int kk = 0; kk < 64; kk++) {
            const float* ap = &SA[kk * 65 + (ty << 2)];
            float a0 = ap[0], a1 = ap[1], a2 = ap[2], a3 = ap[3];
            float4 bv = *(const float4*)(&SB[(kk << 6) + (tx << 2)]);
            acc[0][0]+=a0*bv.x; acc[0][1]+=a0*bv.y; acc[0][2]+=a0*bv.z; acc[0][3]+=a0*bv.w;
            acc[1][0]+=a1*bv.x; acc[1][1]+=a1*bv.y; acc[1][2]+=a1*bv.z; acc[1][3]+=a1*bv.w;
            acc[2][0]+=a2*bv.x; acc[2][1]+=a2*bv.y; acc[2][2]+=a2*bv.z; acc[2][3]+=a2*bv.w;
            acc[3][0]+=a3*bv.x; acc[3][1]+=a3*bv.y; acc[3][2]+=a3*bv.z; acc[3][3]+=a3*bv.w;
        }
        float* O = out + ((long)b * SS + (long)chunk * CHK) * DD;
#pragma unroll
        for (int i = 0; i < 4; i++) {
            long row = (ty << 2) + i;
#pragma unroll
            for (int j = 0; j < 4; j++) {
                long idx = row * DD + n0 + (tx << 2) + j;
                O[idx] = O[idx] - LRc * acc[i][j];
            }
        }
    } else {
        int t2 = x - 16;
        int e0 = (t2 >> 4) << 6;
        int d0 = (t2 & 15) << 6;
        const float* Kb = Kmat + ((long)b * SS + (long)chunk * CHK) * DD;
        for (int i = tid; i < 4096; i += 256) {
            int r = i >> 6, c = i & 63;
            SA[r * 65 + c] = Gb[(long)r * DD + e0 + c];
            SB[(r << 6) + c] = Kb[(long)r * DD + d0 + c];
        }
        __syncthreads();
#pragma unroll 16
        for (int kk = 0; kk < 64; kk++) {
            const float* ap = &SA[kk * 65 + (ty << 2)];
            float a0 = ap[0], a1 = ap[1], a2 = ap[2], a3 = ap[3];
            float4 bv = *(const float4*)(&SB[(kk << 6) + (tx << 2)]);
            acc[0][0]+=a0*bv.x; acc[0][1]+=a0*bv.y; acc[0][2]+=a0*bv.z; acc[0][3]+=a0*bv.w;
            acc[1][0]+=a1*bv.x; acc[1][1]+=a1*bv.y; acc[1][2]+=a1*bv.z; acc[1][3]+=a1*bv.w;
            acc[2][0]+=a2*bv.x; acc[2][1]+=a2*bv.y; acc[2][2]+=a2*bv.z; acc[2][3]+=a2*bv.w;
            acc[3][0]+=a3*bv.x; acc[3][1]+=a3*bv.y; acc[3][2]+=a3*bv.z; acc[3][3]+=a3*bv.w;
        }
        float* Mb = Mm + (long)b * DD * DD;
#pragma unroll
        for (int i = 0; i < 4; i++) {
            long row = e0 + (ty << 2) + i;
#pragma unroll
            for (int j = 0; j < 4; j++) {
                long idx = row * DD + d0 + (tx << 2) + j;
                Mb[idx] += acc[i][j];
            }
        }
    }
}

// ---------------- zero scratch ----------------
__global__ void zero_kernel(float* __restrict__ p, long n)
{
    long i = (long)blockIdx.x * blockDim.x + threadIdx.x;
    long stride = (long)gridDim.x * blockDim.x;
    for (; i < n; i += stride) p[i] = 0.f;
}

// =====================================================================
// host launcher
// =====================================================================
extern "C" void kernel_launch(void* const* d_in, const int* in_sizes, int n_in,
                              void* d_out, int out_size)
{
    (void)in_sizes; (void)n_in; (void)out_size;
    const float* in_seq = (const float*)d_in[0];
    const float* thK = (const float*)d_in[1];
    const float* thV = (const float*)d_in[2];
    const float* thQ = (const float*)d_in[3];
    const float* W0  = (const float*)d_in[4];
    const float* b0  = (const float*)d_in[5];
    float* out = (float*)d_out;

    float *pK, *pQ, *pU, *pM, *ps, *pG, *pUp, *pSkk, *pAqk, *pTi, *pE, *pF;
    cudaGetSymbolAddress((void**)&pK, g_K);
    cudaGetSymbolAddress((void**)&pQ, g_Q);
    cudaGetSymbolAddress((void**)&pU, g_U);
    cudaGetSymbolAddress((void**)&pM, g_M);
    cudaGetSymbolAddress((void**)&ps, g_s);
    cudaGetSymbolAddress((void**)&pG, g_G);
    cudaGetSymbolAddress((void**)&pUp, g_Up);
    cudaGetSymbolAddress((void**)&pSkk, g_Skk);
    cudaGetSymbolAddress((void**)&pAqk, g_Aqk);
    cudaGetSymbolAddress((void**)&pTi, g_Ti);
    cudaGetSymbolAddress((void**)&pE, g_E);
    cudaGetSymbolAddress((void**)&pF, g_F);

    // fold W0 into projections: E = W0@thK - thV, F = W0@thQ
    dim3 g16(16, 16, 1);
    gemm_nn<<<g16, 256>>>(W0, DD, thK, DD, pE, DD, thV, -1.f, 1.f, DD);
    gemm_nn<<<g16, 256>>>(W0, DD, thQ, DD, pF, DD, nullptr, 0.f, 1.f, DD);

    // big projections: X = in_seq [16384,1024]
    dim3 gp(16, (BB * SS) / 64, 1);
    gemm_nt<<<gp, 256>>>(in_seq, DD, thK, DD, pK, DD, nullptr, 1.f, DD);     // K
    gemm_nt<<<gp, 256>>>(in_seq, DD, thQ, DD, pQ, DD, nullptr, 1.f, DD);     // Q
    gemm_nt<<<gp, 256>>>(in_seq, DD, pE,  DD, pU, DD, b0,     GSC, DD);      // U = (2/D)(X E^T + b0)
    gemm_nt<<<gp, 256>>>(in_seq, DD, pF,  DD, out, DD, b0,    1.f, DD);      // out = X F^T + b0

    // Gram matrices + triangular inverses (all chunks up front)
    dim3 gpair(NCHK, 2, BB);
    pair_kernel<<<gpair, 256>>>(pK, pQ, pSkk, pAqk);
    tinv_kernel<<<BB * NCHK, 64>>>(pSkk, pTi);

    // zero state
    zero_kernel<<<512, 256>>>(pM, (long)BB * DD * DD);
    zero_kernel<<<8, 256>>>(ps, (long)BB * DD);

    // chunk loop
    dim3 gc(16, 2, BB);
    dim3 gs(16, BB);
    dim3 gz(16 + 256, BB);
    for (int c = 0; c < NCHK; c++) {
        cross_kernel<<<gc, 256>>>(c, pK, pQ, pU, pM, ps, pUp, out);
        solve_kernel<<<gs, 256>>>(c, pTi, pUp, pG, ps);
        z2_kernel<<<gz, 256>>>(c, pAqk, pG, pK, out, pM);
    }
}

// round 7
// speedup vs baseline: 1.4090x; 1.4090x over previous
#include <cuda_runtime.h>

#define BB   8
#define SS   2048
#define DD   1024
#define CHK  128
#define NCHK (SS / CHK)              // 16
#define LRc  0.01f
#define LAM  (2.0f * 0.01f / 1024.0f)
#define GSC  (2.0f / 1024.0f)

typedef unsigned long long ull;

// ---------------- packed f32x2 helpers ----------------
__device__ __forceinline__ ull dupf(float x) {
    ull r; asm("mov.b64 %0, {%1, %1};" : "=l"(r) : "f"(x)); return r;
}
__device__ __forceinline__ void ffma2(ull& d, ull a, ull b) {
    asm("fma.rn.f32x2 %0, %1, %2, %0;" : "+l"(d) : "l"(a), "l"(b));
}
__device__ __forceinline__ float2 unp(ull v) {
    float lo, hi; asm("mov.b64 {%0, %1}, %2;" : "=f"(lo), "=f"(hi) : "l"(v));
    return make_float2(lo, hi);
}
union F4U { float4 f; ull u[2]; };

// 4 rows x 8 cols micro-step
__device__ __forceinline__ void mm4x8(ull acc[][4], float4 av, const F4U& B0, const F4U& B1) {
    ull a0 = dupf(av.x), a1 = dupf(av.y), a2 = dupf(av.z), a3 = dupf(av.w);
    ffma2(acc[0][0], a0, B0.u[0]); ffma2(acc[0][1], a0, B0.u[1]); ffma2(acc[0][2], a0, B1.u[0]); ffma2(acc[0][3], a0, B1.u[1]);
    ffma2(acc[1][0], a1, B0.u[0]); ffma2(acc[1][1], a1, B0.u[1]); ffma2(acc[1][2], a1, B1.u[0]); ffma2(acc[1][3], a1, B1.u[1]);
    ffma2(acc[2][0], a2, B0.u[0]); ffma2(acc[2][1], a2, B0.u[1]); ffma2(acc[2][2], a2, B1.u[0]); ffma2(acc[2][3], a2, B1.u[1]);
    ffma2(acc[3][0], a3, B0.u[0]); ffma2(acc[3][1], a3, B0.u[1]); ffma2(acc[3][2], a3, B1.u[0]); ffma2(acc[3][3], a3, B1.u[1]);
}

// ---------------- static device scratch ----------------
__device__ float g_K [BB * SS * DD];
__device__ float g_Q [BB * SS * DD];
__device__ float g_U [BB * SS * DD];
__device__ float g_M [BB * DD * DD];
__device__ float g_s [BB * DD];
__device__ float g_G [BB * CHK * DD];
__device__ float g_Up[BB * CHK * DD];
__device__ float g_Skk[BB * NCHK * CHK * CHK];
__device__ float g_Aqk[BB * NCHK * CHK * CHK];
__device__ float g_Ti [BB * NCHK * CHK * CHK];
__device__ float g_E [DD * DD];
__device__ float g_F [DD * DD];

// =====================================================================
// NN GEMM 64x64 (E/F precompute only): C = alpha*A@B + beta*Cin
// =====================================================================
__global__ void __launch_bounds__(256) gemm_nn(
    const float* __restrict__ A, int lda,
    const float* __restrict__ Bm, int ldb,
    float* __restrict__ C, int ldc,
    const float* __restrict__ Cin, float beta, float alpha, int K)
{
    int m0 = blockIdx.y << 6, n0 = blockIdx.x << 6;
    __shared__ float As[32][68];
    __shared__ float Bs[32][68];
    int tid = threadIdx.x;
    int tx = tid & 15, ty = tid >> 4;
    int lr = tid >> 3, lc = (tid & 7) << 2;
    int bkr = tid >> 4, bc = (tid & 15) << 2;
    const float* Ap = A  + (long)(m0 + lr) * lda + lc;
    const float* Bp = Bm + (long)bkr * ldb + n0 + bc;
    float acc[4][4] = {};
    for (int kb = 0; kb < K; kb += 32) {
        float4 a0 = *(const float4*)(Ap + kb);
        float4 a1 = *(const float4*)(Ap + kb + (long)32 * lda);
        float4 bv0 = *(const float4*)(Bp + (long)kb * ldb);
        float4 bv1 = *(const float4*)(Bp + (long)(kb + 16) * ldb);
        __syncthreads();
        As[lc+0][lr]=a0.x; As[lc+1][lr]=a0.y; As[lc+2][lr]=a0.z; As[lc+3][lr]=a0.w;
        As[lc+0][lr+32]=a1.x; As[lc+1][lr+32]=a1.y; As[lc+2][lr+32]=a1.z; As[lc+3][lr+32]=a1.w;
        *(float4*)(&Bs[bkr][bc])      = bv0;
        *(float4*)(&Bs[bkr + 16][bc]) = bv1;
        __syncthreads();
#pragma unroll
        for (int kk = 0; kk < 32; kk++) {
            float4 av = *(const float4*)(&As[kk][ty << 2]);
            float4 bv = *(const float4*)(&Bs[kk][tx << 2]);
            acc[0][0]+=av.x*bv.x; acc[0][1]+=av.x*bv.y; acc[0][2]+=av.x*bv.z; acc[0][3]+=av.x*bv.w;
            acc[1][0]+=av.y*bv.x; acc[1][1]+=av.y*bv.y; acc[1][2]+=av.y*bv.z; acc[1][3]+=av.y*bv.w;
            acc[2][0]+=av.z*bv.x; acc[2][1]+=av.z*bv.y; acc[2][2]+=av.z*bv.z; acc[2][3]+=av.z*bv.w;
            acc[3][0]+=av.w*bv.x; acc[3][1]+=av.w*bv.y; acc[3][2]+=av.w*bv.z; acc[3][3]+=av.w*bv.w;
        }
    }
#pragma unroll
    for (int i = 0; i < 4; i++) {
        long row = m0 + (ty << 2) + i;
#pragma unroll
        for (int j = 0; j < 4; j++) {
            int col = n0 + (tx << 2) + j;
            float v = alpha * acc[i][j];
            if (beta != 0.f) v += beta * Cin[row * ldc + col];
            C[row * ldc + col] = v;
        }
    }
}

// =====================================================================
// Big NT GEMM: 128x128 tile, BK=16, f32x2.  C = alpha*(A@B^T + bias)
// =====================================================================
__global__ void __launch_bounds__(256, 2) gemm_nt_big(
    const float* __restrict__ A, const float* __restrict__ B,
    float* __restrict__ C, const float* __restrict__ bias, float alpha)
{
    int m0 = blockIdx.y << 7, n0 = blockIdx.x << 7;
    __shared__ float SA[16][132];
    __shared__ float SB[16][132];
    int tid = threadIdx.x;
    int tx = tid & 15, ty = tid >> 4;
    int ar = tid >> 2, ac = (tid & 3) << 2;
    const float* Ap = A + (long)(m0 + ar) * DD + ac;
    const float* Bp = B + (long)(n0 + ar) * DD + ac;
    ull acc[8][4] = {};
    for (int kb = 0; kb < DD; kb += 16) {
        float4 a0 = *(const float4*)(Ap + kb);
        float4 a1 = *(const float4*)(Ap + kb + (long)64 * DD);
        float4 b0 = *(const float4*)(Bp + kb);
        float4 b1 = *(const float4*)(Bp + kb + (long)64 * DD);
        __syncthreads();
        SA[ac+0][ar]=a0.x; SA[ac+1][ar]=a0.y; SA[ac+2][ar]=a0.z; SA[ac+3][ar]=a0.w;
        SA[ac+0][ar+64]=a1.x; SA[ac+1][ar+64]=a1.y; SA[ac+2][ar+64]=a1.z; SA[ac+3][ar+64]=a1.w;
        SB[ac+0][ar]=b0.x; SB[ac+1][ar]=b0.y; SB[ac+2][ar]=b0.z; SB[ac+3][ar]=b0.w;
        SB[ac+0][ar+64]=b1.x; SB[ac+1][ar+64]=b1.y; SB[ac+2][ar+64]=b1.z; SB[ac+3][ar+64]=b1.w;
        __syncthreads();
#pragma unroll
        for (int kk = 0; kk < 16; kk++) {
            float4 av0 = *(const float4*)&SA[kk][ty << 2];
            float4 av1 = *(const float4*)&SA[kk][64 + (ty << 2)];
            F4U B0, B1;
            B0.f = *(const float4*)&SB[kk][tx << 2];
            B1.f = *(const float4*)&SB[kk][64 + (tx << 2)];
            mm4x8(&acc[0], av0, B0, B1);
            mm4x8(&acc[4], av1, B0, B1);
        }
    }
    int c0 = n0 + (tx << 2), c1 = c0 + 64;
    float bb[8];
#pragma unroll
    for (int j = 0; j < 4; j++) { bb[j] = bias ? bias[c0 + j] : 0.f; bb[4+j] = bias ? bias[c1 + j] : 0.f; }
#pragma unroll
    for (int i = 0; i < 8; i++) {
        long row = m0 + ((i < 4) ? ((ty << 2) + i) : (64 + (ty << 2) + i - 4));
        float2 p0 = unp(acc[i][0]), p1 = unp(acc[i][1]), p2 = unp(acc[i][2]), p3 = unp(acc[i][3]);
        float4 w0 = make_float4(alpha*(p0.x+bb[0]), alpha*(p0.y+bb[1]), alpha*(p1.x+bb[2]), alpha*(p1.y+bb[3]));
        float4 w1 = make_float4(alpha*(p2.x+bb[4]), alpha*(p2.y+bb[5]), alpha*(p3.x+bb[6]), alpha*(p3.y+bb[7]));
        *(float4*)(C + row * DD + c0) = w0;
        *(float4*)(C + row * DD + c1) = w1;
    }
}

// =====================================================================
// Pair: per (b,chunk) Skk = Kc@Kc^T, Aqk = Qc@Kc^T  (128x128, K=1024)
// =====================================================================
__global__ void __launch_bounds__(256) pair_kernel(
    const float* __restrict__ Km, const float* __restrict__ Qm,
    float* __restrict__ Skk, float* __restrict__ Aqk)
{
    int z = blockIdx.z;
    int rt = blockIdx.x, which = blockIdx.y;
    long co = ((long)(z / NCHK) * SS + (long)(z % NCHK) * CHK) * DD;
    const float* A  = (which ? Qm : Km) + co + (long)rt * 64 * DD;
    const float* Bm = Km + co;
    float* C = (which ? Aqk : Skk) + (long)z * CHK * CHK + (long)rt * 64 * CHK;

    __shared__ float SA[16][68];
    __shared__ float SB[16][132];
    int tid = threadIdx.x, tx = tid & 15, ty = tid >> 4;
    int ar = tid >> 2, ac = (tid & 3) << 2;
    const float* Ap = A  + (long)ar * DD + ac;
    const float* Bp = Bm + (long)ar * DD + ac;
    ull acc[4][4] = {};
    for (int kb = 0; kb < DD; kb += 16) {
        float4 a0 = *(const float4*)(Ap + kb);
        float4 b0 = *(const float4*)(Bp + kb);
        float4 b1 = *(const float4*)(Bp + kb + (long)64 * DD);
        __syncthreads();
        SA[ac+0][ar]=a0.x; SA[ac+1][ar]=a0.y; SA[ac+2][ar]=a0.z; SA[ac+3][ar]=a0.w;
        SB[ac+0][ar]=b0.x; SB[ac+1][ar]=b0.y; SB[ac+2][ar]=b0.z; SB[ac+3][ar]=b0.w;
        SB[ac+0][ar+64]=b1.x; SB[ac+1][ar+64]=b1.y; SB[ac+2][ar+64]=b1.z; SB[ac+3][ar+64]=b1.w;
        __syncthreads();
#pragma unroll
        for (int kk = 0; kk < 16; kk++) {
            float4 av = *(const float4*)&SA[kk][ty << 2];
            F4U B0, B1;
            B0.f = *(const float4*)&SB[kk][tx << 2];
            B1.f = *(const float4*)&SB[kk][64 + (tx << 2)];
            mm4x8(acc, av, B0, B1);
        }
    }
    int c0 = (tx << 2), c1 = c0 + 64;
#pragma unroll
    for (int i = 0; i < 4; i++) {
        long row = (ty << 2) + i;
        float2 p0 = unp(acc[i][0]), p1 = unp(acc[i][1]), p2 = unp(acc[i][2]), p3 = unp(acc[i][3]);
        *(float4*)(C + row * CHK + c0) = make_float4(p0.x, p0.y, p1.x, p1.y);
        *(float4*)(C + row * CHK + c1) = make_float4(p2.x, p2.y, p3.x, p3.y);
    }
}

// =====================================================================
// tinv64: invert diagonal 64x64 blocks of L = I + LAM*strict_lower(Skk+1)
// =====================================================================
__global__ void tinv64_kernel(const float* __restrict__ Skk, float* __restrict__ Ti)
{
    int z = blockIdx.y, db = blockIdx.x;
    const float* Ain = Skk + (long)z * CHK * CHK;
    float* T = Ti + (long)z * CHK * CHK;
    __shared__ float A[64][64];
    __shared__ float Ts[64][64];
    int j = threadIdx.x;
    int off = db * 64;
    for (int t = 0; t < 64; t++) A[t][j] = Ain[(long)(off + t) * CHK + off + j] + 1.0f;
    __syncthreads();
    for (int t = 0; t < 64; t++) {
        float v;
        if (t < j) v = 0.f;
        else if (t == j) v = 1.f;
        else {
            float ss = 0.f;
            for (int i = j; i < t; i++) ss += A[t][i] * Ts[i][j];
            v = -LAM * ss;
        }
        Ts[t][j] = v;
    }
    __syncthreads();
    for (int t = 0; t < 64; t++) T[(long)(off + t) * CHK + off + j] = Ts[t][j];
    if (db == 0)
        for (int t = 0; t < 64; t++) T[(long)t * CHK + 64 + j] = 0.f;
}

// =====================================================================
// tcomb: T21 = -T22 @ (LAM*(Skk21+1)) @ T11
// =====================================================================
__global__ void __launch_bounds__(256) tcomb_kernel(
    const float* __restrict__ Skk, float* __restrict__ Ti)
{
    long z = blockIdx.x;
    const float* Sk = Skk + z * CHK * CHK;
    float* T = Ti + z * CHK * CHK;
    __shared__ float T11[64 * 64];
    __shared__ float T22[64 * 64];
    __shared__ float X  [64 * 64];
    int tid = threadIdx.x;
    for (int i = tid; i < 4096; i += 256) {
        int r = i >> 6, c = i & 63;
        T11[i] = T[(long)r * CHK + c];
        T22[i] = T[(long)(64 + r) * CHK + 64 + c];
    }
    __syncthreads();
    int t = tid >> 2, jg = (tid & 3) << 4;
    float xr[16];
#pragma unroll
    for (int j = 0; j < 16; j++) xr[j] = 0.f;
    for (int i = 0; i < 64; i++) {
        float l = LAM * (Sk[(long)(64 + t) * CHK + i] + 1.0f);
#pragma unroll
        for (int j = 0; j < 16; j++) xr[j] += l * T11[(i << 6) + jg + j];
    }
#pragma unroll
    for (int j = 0; j < 16; j++) X[(t << 6) + jg + j] = xr[j];
    __syncthreads();
    float yr[16];
#pragma unroll
    for (int j = 0; j < 16; j++) yr[j] = 0.f;
    for (int i = 0; i < 64; i++) {
        float l = T22[(t << 6) + i];
#pragma unroll
        for (int j = 0; j < 16; j++) yr[j] += l * X[(i << 6) + jg + j];
    }
#pragma unroll
    for (int j = 0; j < 16; j++) T[(long)(64 + t) * CHK + jg + j] = -yr[j];
}

// =====================================================================
// Cross per chunk: grp0: Up = U_c - LAM*(Kc@M^T + s); grp1: out -= LR*(Qc@M^T + s)
// =====================================================================
__global__ void __launch_bounds__(256) cross_kernel(int chunk,
    const float* __restrict__ Km, const float* __restrict__ Qm,
    const float* __restrict__ U, const float* __restrict__ Mm,
    const float* __restrict__ s, float* __restrict__ Up, float* __restrict__ out)
{
    int b = blockIdx.z;
    int grp = blockIdx.y >> 1, rt = blockIdx.y & 1;
    int n0 = blockIdx.x << 7;
    long rowoff = ((long)b * SS + (long)chunk * CHK + rt * 64) * DD;
    const float* A; const float* Cin; float* Co; float alpha;
    if (grp == 0) { A = Km + rowoff; Cin = U + rowoff;   Co = Up + ((long)b * CHK + rt * 64) * DD; alpha = -LAM; }
    else          { A = Qm + rowoff; Cin = out + rowoff; Co = out + rowoff;                        alpha = -LRc; }
    const float* Bm = Mm + (long)b * DD * DD;
    const float* sb = s + (long)b * DD;

    __shared__ float SA[16][68];
    __shared__ float SB[16][132];
    int tid = threadIdx.x, tx = tid & 15, ty = tid >> 4;
    int ar = tid >> 2, ac = (tid & 3) << 2;
    const float* Ap = A  + (long)ar * DD + ac;
    const float* Bp = Bm + (long)(n0 + ar) * DD + ac;
    ull acc[4][4] = {};
    for (int kb = 0; kb < DD; kb += 16) {
        float4 a0 = *(const float4*)(Ap + kb);
        float4 b0 = *(const float4*)(Bp + kb);
        float4 b1 = *(const float4*)(Bp + kb + (long)64 * DD);
        __syncthreads();
        SA[ac+0][ar]=a0.x; SA[ac+1][ar]=a0.y; SA[ac+2][ar]=a0.z; SA[ac+3][ar]=a0.w;
        SB[ac+0][ar]=b0.x; SB[ac+1][ar]=b0.y; SB[ac+2][ar]=b0.z; SB[ac+3][ar]=b0.w;
        SB[ac+0][ar+64]=b1.x; SB[ac+1][ar+64]=b1.y; SB[ac+2][ar+64]=b1.z; SB[ac+3][ar+64]=b1.w;
        __syncthreads();
#pragma unroll
        for (int kk = 0; kk < 16; kk++) {
            float4 av = *(const float4*)&SA[kk][ty << 2];
            F4U B0, B1;
            B0.f = *(const float4*)&SB[kk][tx << 2];
            B1.f = *(const float4*)&SB[kk][64 + (tx << 2)];
            mm4x8(acc, av, B0, B1);
        }
    }
    int c0 = n0 + (tx << 2), c1 = c0 + 64;
    float s00 = sb[c0], s01 = sb[c0+1], s02 = sb[c0+2], s03 = sb[c0+3];
    float s10 = sb[c1], s11 = sb[c1+1], s12 = sb[c1+2], s13 = sb[c1+3];
#pragma unroll
    for (int i = 0; i < 4; i++) {
        long row = (ty << 2) + i;
        float2 p0 = unp(acc[i][0]), p1 = unp(acc[i][1]), p2 = unp(acc[i][2]), p3 = unp(acc[i][3]);
        float4 i0 = *(const float4*)(Cin + row * DD + c0);
        float4 i1 = *(const float4*)(Cin + row * DD + c1);
        float4 w0 = make_float4(i0.x + alpha*(p0.x+s00), i0.y + alpha*(p0.y+s01),
                                i0.z + alpha*(p1.x+s02), i0.w + alpha*(p1.y+s03));
        float4 w1 = make_float4(i1.x + alpha*(p2.x+s10), i1.y + alpha*(p2.y+s11),
                                i1.z + alpha*(p3.x+s12), i1.w + alpha*(p3.y+s13));
        *(float4*)(Co + row * DD + c0) = w0;
        *(float4*)(Co + row * DD + c1) = w1;
    }
}

// =====================================================================
// Solve: G = Ti @ Up  (128x1024, K=128)
// =====================================================================
__global__ void __launch_bounds__(256) solve_kernel(int chunk,
    const float* __restrict__ Ti, const float* __restrict__ Up, float* __restrict__ G)
{
    int b = blockIdx.z, rt = blockIdx.y, n0 = blockIdx.x << 7;
    const float* T = Ti + ((long)b * NCHK + chunk) * CHK * CHK + (long)rt * 64 * CHK;
    const float* B = Up + (long)b * CHK * DD;
    float* Gb = G + (long)b * CHK * DD + (long)rt * 64 * DD;
    __shared__ float SA[16][68];
    __shared__ float SB[16][132];
    int tid = threadIdx.x, tx = tid & 15, ty = tid >> 4;
    int ar = tid >> 2, ac = (tid & 3) << 2;
    int kr = tid >> 5, bc = (tid & 31) << 2;
    ull acc[4][4] = {};
    for (int kb = 0; kb < CHK; kb += 16) {
        float4 a0 = *(const float4*)(T + (long)ar * CHK + kb + ac);
        float4 b0 = *(const float4*)(B + (long)(kb + kr) * DD + n0 + bc);
        float4 b1 = *(const float4*)(B + (long)(kb + kr + 8) * DD + n0 + bc);
        __syncthreads();
        SA[ac+0][ar]=a0.x; SA[ac+1][ar]=a0.y; SA[ac+2][ar]=a0.z; SA[ac+3][ar]=a0.w;
        *(float4*)&SB[kr][bc] = b0;
        *(float4*)&SB[kr + 8][bc] = b1;
        __syncthreads();
#pragma unroll
        for (int kk = 0; kk < 16; kk++) {
            float4 av = *(const float4*)&SA[kk][ty << 2];
            F4U B0, B1;
            B0.f = *(const float4*)&SB[kk][tx << 2];
            B1.f = *(const float4*)&SB[kk][64 + (tx << 2)];
            mm4x8(acc, av, B0, B1);
        }
    }
    int c0 = n0 + (tx << 2), c1 = c0 + 64;
#pragma unroll
    for (int i = 0; i < 4; i++) {
        long row = (ty << 2) + i;
        float2 p0 = unp(acc[i][0]), p1 = unp(acc[i][1]), p2 = unp(acc[i][2]), p3 = unp(acc[i][3]);
        *(float4*)(Gb + row * DD + c0) = make_float4(p0.x, p0.y, p1.x, p1.y);
        *(float4*)(Gb + row * DD + c1) = make_float4(p2.x, p2.y, p3.x, p3.y);
    }
}

// =====================================================================
// Z2a: out_c -= LR * (masked(Aqk+1)) @ G   (128x1024, K=128)
// =====================================================================
__global__ void __launch_bounds__(256) z2a_kernel(int chunk,
    const float* __restrict__ Aqk, const float* __restrict__ G, float* __restrict__ out)
{
    int b = blockIdx.z, rt = blockIdx.y, n0 = blockIdx.x << 7;
    const float* Aq = Aqk + ((long)b * NCHK + chunk) * CHK * CHK;
    const float* B = G + (long)b * CHK * DD;
    float* O = out + ((long)b * SS + (long)chunk * CHK + rt * 64) * DD;
    __shared__ float SA[16][68];
    __shared__ float SB[16][132];
    int tid = threadIdx.x, tx = tid & 15, ty = tid >> 4;
    int ar = tid >> 2, ac = (tid & 3) << 2;
    int kr = tid >> 5, bc = (tid & 31) << 2;
    int tglob = rt * 64 + ar;
    ull acc[4][4] = {};
    for (int kb = 0; kb < CHK; kb += 16) {
        float4 a0 = *(const float4*)(Aq + (long)tglob * CHK + kb + ac);
        float4 b0 = *(const float4*)(B + (long)(kb + kr) * DD + n0 + bc);
        float4 b1 = *(const float4*)(B + (long)(kb + kr + 8) * DD + n0 + bc);
        __syncthreads();
        int i0 = kb + ac;
        SA[ac+0][ar] = (i0+0 <= tglob) ? a0.x + 1.0f : 0.f;
        SA[ac+1][ar] = (i0+1 <= tglob) ? a0.y + 1.0f : 0.f;
        SA[ac+2][ar] = (i0+2 <= tglob) ? a0.z + 1.0f : 0.f;
        SA[ac+3][ar] = (i0+3 <= tglob) ? a0.w + 1.0f : 0.f;
        *(float4*)&SB[kr][bc] = b0;
        *(float4*)&SB[kr + 8][bc] = b1;
        __syncthreads();
#pragma unroll
        for (int kk = 0; kk < 16; kk++) {
            float4 av = *(const float4*)&SA[kk][ty << 2];
            F4U B0, B1;
            B0.f = *(const float4*)&SB[kk][tx << 2];
            B1.f = *(const float4*)&SB[kk][64 + (tx << 2)];
            mm4x8(acc, av, B0, B1);
        }
    }
    int c0 = n0 + (tx << 2), c1 = c0 + 64;
#pragma unroll
    for (int i = 0; i < 4; i++) {
        long row = (ty << 2) + i;
        float2 p0 = unp(acc[i][0]), p1 = unp(acc[i][1]), p2 = unp(acc[i][2]), p3 = unp(acc[i][3]);
        float4 o0 = *(const float4*)(O + row * DD + c0);
        float4 o1 = *(const float4*)(O + row * DD + c1);
        o0.x -= LRc * p0.x; o0.y -= LRc * p0.y; o0.z -= LRc * p1.x; o0.w -= LRc * p1.y;
        o1.x -= LRc * p2.x; o1.y -= LRc * p2.y; o1.z -= LRc * p3.x; o1.w -= LRc * p3.y;
        *(float4*)(O + row * DD + c0) = o0;
        *(float4*)(O + row * DD + c1) = o1;
    }
}

// =====================================================================
// Z2b: M += G^T @ Kc (1024x1024, K=128); plus colsum(G) into s.
// =====================================================================
__global__ void __launch_bounds__(256, 2) z2b_kernel(int chunk,
    const float* __restrict__ G, const float* __restrict__ Km,
    float* __restrict__ Mm, float* __restrict__ s)
{
    int b = blockIdx.z;
    const float* Ga = G + (long)b * CHK * DD;
    if (blockIdx.y == 8) {
        if (blockIdx.x >= 4) return;
        int col = (blockIdx.x << 8) + threadIdx.x;
        float t = 0.f;
#pragma unroll 8
        for (int r = 0; r < CHK; r++) t += Ga[(long)r * DD + col];
        s[(long)b * DD + col] += t;
        return;
    }
    int e0 = blockIdx.x << 7, d0 = blockIdx.y << 7;
    const float* Kc = Km + ((long)b * SS + (long)chunk * CHK) * DD;
    float* Mb = Mm + (long)b * DD * DD;
    __shared__ float SA[16][132];
    __shared__ float SB[16][132];
    int tid = threadIdx.x, tx = tid & 15, ty = tid >> 4;
    int kr = tid >> 5, bc = (tid & 31) << 2;
    ull acc[8][4] = {};
    for (int kb = 0; kb < CHK; kb += 16) {
        float4 a0 = *(const float4*)(Ga + (long)(kb + kr) * DD + e0 + bc);
        float4 a1 = *(const float4*)(Ga + (long)(kb + kr + 8) * DD + e0 + bc);
        float4 b0 = *(const float4*)(Kc + (long)(kb + kr) * DD + d0 + bc);
        float4 b1 = *(const float4*)(Kc + (long)(kb + kr + 8) * DD + d0 + bc);
        __syncthreads();
        *(float4*)&SA[kr][bc] = a0; *(float4*)&SA[kr + 8][bc] = a1;
        *(float4*)&SB[kr][bc] = b0; *(float4*)&SB[kr + 8][bc] = b1;
        __syncthreads();
#pragma unroll
        for (int kk = 0; kk < 16; kk++) {
            float4 av0 = *(const float4*)&SA[kk][ty << 2];
            float4 av1 = *(const float4*)&SA[kk][64 + (ty << 2)];
            F4U B0, B1;
            B0.f = *(const float4*)&SB[kk][tx << 2];
            B1.f = *(const float4*)&SB[kk][64 + (tx << 2)];
            mm4x8(&acc[0], av0, B0, B1);
            mm4x8(&acc[4], av1, B0, B1);
        }
    }
    int c0 = d0 + (tx << 2), c1 = c0 + 64;
#pragma unroll
    for (int i = 0; i < 8; i++) {
        long row = e0 + ((i < 4) ? ((ty << 2) + i) : (64 + (ty << 2) + i - 4));
        float2 p0 = unp(acc[i][0]), p1 = unp(acc[i][1]), p2 = unp(acc[i][2]), p3 = unp(acc[i][3]);
        float4 m0 = *(const float4*)(Mb + row * DD + c0);
        float4 m1 = *(const float4*)(Mb + row * DD + c1);
        m0.x += p0.x; m0.y += p0.y; m0.z += p1.x; m0.w += p1.y;
        m1.x += p2.x; m1.y += p2.y; m1.z += p3.x; m1.w += p3.y;
        *(float4*)(Mb + row * DD + c0) = m0;
        *(float4*)(Mb + row * DD + c1) = m1;
    }
}

__global__ void zero_kernel(float* __restrict__ p, long n)
{
    long i = (long)blockIdx.x * blockDim.x + threadIdx.x;
    long stride = (long)gridDim.x * blockDim.x;
    for (; i < n; i += stride) p[i] = 0.f;
}

// =====================================================================
// host launcher
// =====================================================================
extern "C" void kernel_launch(void* const* d_in, const int* in_sizes, int n_in,
                              void* d_out, int out_size)
{
    (void)in_sizes; (void)n_in; (void)out_size;
    const float* in_seq = (const float*)d_in[0];
    const float* thK = (const float*)d_in[1];
    const float* thV = (const float*)d_in[2];
    const float* thQ = (const float*)d_in[3];
    const float* W0  = (const float*)d_in[4];
    const float* b0  = (const float*)d_in[5];
    float* out = (float*)d_out;

    float *pK, *pQ, *pU, *pM, *ps, *pG, *pUp, *pSkk, *pAqk, *pTi, *pE, *pF;
    cudaGetSymbolAddress((void**)&pK, g_K);
    cudaGetSymbolAddress((void**)&pQ, g_Q);
    cudaGetSymbolAddress((void**)&pU, g_U);
    cudaGetSymbolAddress((void**)&pM, g_M);
    cudaGetSymbolAddress((void**)&ps, g_s);
    cudaGetSymbolAddress((void**)&pG, g_G);
    cudaGetSymbolAddress((void**)&pUp, g_Up);
    cudaGetSymbolAddress((void**)&pSkk, g_Skk);
    cudaGetSymbolAddress((void**)&pAqk, g_Aqk);
    cudaGetSymbolAddress((void**)&pTi, g_Ti);
    cudaGetSymbolAddress((void**)&pE, g_E);
    cudaGetSymbolAddress((void**)&pF, g_F);

    // E = W0@thK - thV, F = W0@thQ
    dim3 g16(16, 16, 1);
    gemm_nn<<<g16, 256>>>(W0, DD, thK, DD, pE, DD, thV, -1.f, 1.f, DD);
    gemm_nn<<<g16, 256>>>(W0, DD, thQ, DD, pF, DD, nullptr, 0.f, 1.f, DD);

    // big projections
    dim3 gb(DD / 128, (BB * SS) / 128, 1);
    gemm_nt_big<<<gb, 256>>>(in_seq, thK, pK, nullptr, 1.f);
    gemm_nt_big<<<gb, 256>>>(in_seq, thQ, pQ, nullptr, 1.f);
    gemm_nt_big<<<gb, 256>>>(in_seq, pE,  pU, b0, GSC);
    gemm_nt_big<<<gb, 256>>>(in_seq, pF,  out, b0, 1.f);

    // Gram matrices + triangular inverses
    pair_kernel<<<dim3(2, 2, BB * NCHK), 256>>>(pK, pQ, pSkk, pAqk);
    tinv64_kernel<<<dim3(2, BB * NCHK), 64>>>(pSkk, pTi);
    tcomb_kernel<<<BB * NCHK, 256>>>(pSkk, pTi);

    // zero state
    zero_kernel<<<512, 256>>>(pM, (long)BB * DD * DD);
    zero_kernel<<<8, 256>>>(ps, (long)BB * DD);

    // chunk loop
    for (int c = 0; c < NCHK; c++) {
        cross_kernel<<<dim3(8, 4, BB), 256>>>(c, pK, pQ, pU, pM, ps, pUp, out);
        solve_kernel<<<dim3(8, 2, BB), 256>>>(c, pTi, pUp, pG);
        z2a_kernel<<<dim3(8, 2, BB), 256>>>(c, pAqk, pG, out);
        z2b_kernel<<<dim3(8, 9, BB), 256>>>(c, pG, pK, pM, ps);
    }
}

// round 9
// speedup vs baseline: 1.6207x; 1.1503x over previous
#include <cuda_runtime.h>
#include <cuda_bf16.h>
#include <cstdint>

#define BB   8
#define SS   2048
#define DD   1024
#define CHK  128
#define NCHK (SS / CHK)              // 16
#define LRc  0.01f
#define LAM  (2.0f * 0.01f / 1024.0f)
#define GSC  (2.0f / 1024.0f)
#define K3   3072                    // packed split-bf16 K
#define NKB  (K3 / 32)               // 96 k-blocks of 32

typedef unsigned long long ull;

// ---------------- packed f32x2 helpers (SIMT kernels) ----------------
__device__ __forceinline__ ull dupf(float x) {
    ull r; asm("mov.b64 %0, {%1, %1};" : "=l"(r) : "f"(x)); return r;
}
__device__ __forceinline__ void ffma2(ull& d, ull a, ull b) {
    asm("fma.rn.f32x2 %0, %1, %2, %0;" : "+l"(d) : "l"(a), "l"(b));
}
__device__ __forceinline__ float2 unp(ull v) {
    float lo, hi; asm("mov.b64 {%0, %1}, %2;" : "=f"(lo), "=f"(hi) : "l"(v));
    return make_float2(lo, hi);
}
union F4U { float4 f; ull u[2]; };

__device__ __forceinline__ void mm4x8(ull acc[][4], float4 av, const F4U& B0, const F4U& B1) {
    ull a0 = dupf(av.x), a1 = dupf(av.y), a2 = dupf(av.z), a3 = dupf(av.w);
    ffma2(acc[0][0], a0, B0.u[0]); ffma2(acc[0][1], a0, B0.u[1]); ffma2(acc[0][2], a0, B1.u[0]); ffma2(acc[0][3], a0, B1.u[1]);
    ffma2(acc[1][0], a1, B0.u[0]); ffma2(acc[1][1], a1, B0.u[1]); ffma2(acc[1][2], a1, B1.u[0]); ffma2(acc[1][3], a1, B1.u[1]);
    ffma2(acc[2][0], a2, B0.u[0]); ffma2(acc[2][1], a2, B0.u[1]); ffma2(acc[2][2], a2, B1.u[0]); ffma2(acc[2][3], a2, B1.u[1]);
    ffma2(acc[3][0], a3, B0.u[0]); ffma2(acc[3][1], a3, B0.u[1]); ffma2(acc[3][2], a3, B1.u[0]); ffma2(acc[3][3], a3, B1.u[1]);
}

// ---------------- HMMA helpers (sm_80 baseline, compiles for compute_103) ----
__device__ __forceinline__ uint32_t smem_u32(const void* p) {
    uint32_t a;
    asm("{ .reg .u64 t; cvta.to.shared.u64 t, %1; cvt.u32.u64 %0, t; }" : "=r"(a) : "l"(p));
    return a;
}
__device__ __forceinline__ void ldm4(uint32_t& r0, uint32_t& r1, uint32_t& r2, uint32_t& r3, uint32_t addr) {
    asm volatile("ldmatrix.sync.aligned.m8n8.x4.shared.b16 {%0,%1,%2,%3}, [%4];"
        : "=r"(r0), "=r"(r1), "=r"(r2), "=r"(r3) : "r"(addr));
}
__device__ __forceinline__ void mma16816(float* d, const uint32_t* a, const uint32_t* b) {
    asm volatile("mma.sync.aligned.m16n8k16.row.col.f32.bf16.bf16.f32 "
        "{%0,%1,%2,%3}, {%4,%5,%6,%7}, {%8,%9}, {%0,%1,%2,%3};"
        : "+f"(d[0]), "+f"(d[1]), "+f"(d[2]), "+f"(d[3])
        : "r"(a[0]), "r"(a[1]), "r"(a[2]), "r"(a[3]), "r"(b[0]), "r"(b[1]));
}

// ---------------- static device scratch ----------------
__device__ float g_K [BB * SS * DD];
__device__ float g_Q [BB * SS * DD];
__device__ float g_U [BB * SS * DD];
__device__ float g_M [BB * DD * DD];
__device__ float g_s [BB * DD];
__device__ float g_G [BB * CHK * DD];
__device__ float g_Up[BB * CHK * DD];
__device__ float g_Skk[BB * NCHK * CHK * CHK];
__device__ float g_Aqk[BB * NCHK * CHK * CHK];
__device__ float g_Ti [BB * NCHK * CHK * CHK];
__device__ float g_E [DD * DD];
__device__ float g_F [DD * DD];
__device__ __nv_bfloat16 g_X2[(long)BB * SS * K3];   // packed [hi|hi|lo]
__device__ __nv_bfloat16 g_WK[DD * K3];              // packed [hi|lo|hi]
__device__ __nv_bfloat16 g_WQ[DD * K3];
__device__ __nv_bfloat16 g_WE[DD * K3];
__device__ __nv_bfloat16 g_WF[DD * K3];

// =====================================================================
// split-bf16 conversion: A-type [hi|hi|lo], B-type [hi|lo|hi]
// =====================================================================
__global__ void cvt_a_kernel(const float* __restrict__ s, __nv_bfloat16* __restrict__ d, long n)
{
    for (long i = (long)blockIdx.x * blockDim.x + threadIdx.x; i < n; i += (long)gridDim.x * blockDim.x) {
        long r = i >> 10; int c = (int)(i & 1023);
        float x = s[i];
        __nv_bfloat16 h = __float2bfloat16(x);
        __nv_bfloat16 l = __float2bfloat16(x - __bfloat162float(h));
        __nv_bfloat16* row = d + r * K3;
        row[c] = h; row[1024 + c] = h; row[2048 + c] = l;
    }
}
__global__ void cvt_b_kernel(const float* __restrict__ s, __nv_bfloat16* __restrict__ d, long n)
{
    for (long i = (long)blockIdx.x * blockDim.x + threadIdx.x; i < n; i += (long)gridDim.x * blockDim.x) {
        long r = i >> 10; int c = (int)(i & 1023);
        float x = s[i];
        __nv_bfloat16 h = __float2bfloat16(x);
        __nv_bfloat16 l = __float2bfloat16(x - __bfloat162float(h));
        __nv_bfloat16* row = d + r * K3;
        row[c] = h; row[1024 + c] = l; row[2048 + c] = h;
    }
}

// =====================================================================
// HMMA NT GEMM: C[m,n] = alpha*(sum_k A2[m,k]*B2[n,k] + bias[n]), K=K3
// 128x128 CTA tile, 8 warps (2x4), warp tile 64x32, BK=32 bf16,
// mma.sync m16n8k16 bf16, padded smem rows (40 bf16) -> conflict-free ldmatrix.
// =====================================================================
#define SROW 40
#define STILE (128 * SROW)           // bf16 elements per buffer

__global__ void __launch_bounds__(256) hmma_nt(
    const __nv_bfloat16* __restrict__ A2, const __nv_bfloat16* __restrict__ B2,
    float* __restrict__ C, const float* __restrict__ bias, float alpha)
{
    __shared__ __nv_bfloat16 SA[2][STILE];
    __shared__ __nv_bfloat16 SB[2][STILE];
    const int tid = threadIdx.x, lane = tid & 31, wid = tid >> 5;
    const int wr = wid >> 2, wc = wid & 3;
    const int m0 = blockIdx.y << 7, n0 = blockIdx.x << 7;
    const int lr = tid >> 1, lc = (tid & 1) << 4;   // loader: row, col(16 bf16)

    const __nv_bfloat16* Ap = A2 + (long)(m0 + lr) * K3 + lc;
    const __nv_bfloat16* Bp = B2 + (long)(n0 + lr) * K3 + lc;
    const uint32_t sa0 = smem_u32(SA), sb0 = smem_u32(SB);

    // ldmatrix per-thread addresses (byte offsets within a buffer)
    // A: row = wr*64 + mt*16 + (lane&15), col = kk + ((lane>>4)<<3)
    const uint32_t a_ro = (uint32_t)(wr * 64 + (lane & 15)) * (SROW * 2) + ((lane >> 4) << 3) * 2;
    // B: nrow = wc*32 + p*16 + ((lane>>4)<<3) + (lane&7), col = kk + (((lane>>3)&1)<<3)
    const uint32_t b_ro = (uint32_t)(wc * 32 + ((lane >> 4) << 3) + (lane & 7)) * (SROW * 2)
                        + (((lane >> 3) & 1) << 3) * 2;

    float acc[4][4][4];
#pragma unroll
    for (int i = 0; i < 4; i++)
#pragma unroll
        for (int j = 0; j < 4; j++)
#pragma unroll
            for (int k = 0; k < 4; k++) acc[i][j][k] = 0.f;

    uint4 ra0, ra1, rb0, rb1;
#define LDG_KB(c) do { \
    ra0 = *(const uint4*)(Ap + (c) * 32); \
    ra1 = *(const uint4*)(Ap + (c) * 32 + 8); \
    rb0 = *(const uint4*)(Bp + (c) * 32); \
    rb1 = *(const uint4*)(Bp + (c) * 32 + 8); } while (0)
#define STS_KB(s) do { \
    *(uint4*)&SA[s][lr * SROW + lc] = ra0; \
    *(uint4*)&SA[s][lr * SROW + lc + 8] = ra1; \
    *(uint4*)&SB[s][lr * SROW + lc] = rb0; \
    *(uint4*)&SB[s][lr * SROW + lc + 8] = rb1; } while (0)

    LDG_KB(0);
    for (int c = 0; c < NKB; c++) {
        int s = c & 1;
        STS_KB(s);
        if (c + 1 < NKB) LDG_KB(c + 1);
        __syncthreads();
        uint32_t abase = sa0 + (uint32_t)s * (STILE * 2) + a_ro;
        uint32_t bbase = sb0 + (uint32_t)s * (STILE * 2) + b_ro;
#pragma unroll
        for (int kk = 0; kk < 2; kk++) {      // two k16 steps per BK=32
            uint32_t af[4][4], bfr[4][2];
#pragma unroll
            for (int mt = 0; mt < 4; mt++)
                ldm4(af[mt][0], af[mt][1], af[mt][2], af[mt][3],
                     abase + (uint32_t)(mt * 16) * (SROW * 2) + kk * 32);
#pragma unroll
            for (int p = 0; p < 2; p++) {
                uint32_t t0, t1, t2, t3;
                ldm4(t0, t1, t2, t3, bbase + (uint32_t)(p * 16) * (SROW * 2) + kk * 32);
                bfr[2 * p][0] = t0; bfr[2 * p][1] = t1;
                bfr[2 * p + 1][0] = t2; bfr[2 * p + 1][1] = t3;
            }
#pragma unroll
            for (int mt = 0; mt < 4; mt++)
#pragma unroll
                for (int nt = 0; nt < 4; nt++)
                    mma16816(acc[mt][nt], af[mt], bfr[nt]);
        }
        __syncthreads();
    }

    // epilogue
#pragma unroll
    for (int mt = 0; mt < 4; mt++) {
        int r = m0 + wr * 64 + mt * 16 + (lane >> 2);
#pragma unroll
        for (int nt = 0; nt < 4; nt++) {
            int cb = n0 + wc * 32 + nt * 8 + ((lane & 3) << 1);
            float b0v = bias ? bias[cb] : 0.f, b1v = bias ? bias[cb + 1] : 0.f;
            float2 w0 = make_float2(alpha * (acc[mt][nt][0] + b0v), alpha * (acc[mt][nt][1] + b1v));
            float2 w1 = make_float2(alpha * (acc[mt][nt][2] + b0v), alpha * (acc[mt][nt][3] + b1v));
            *(float2*)(C + (long)r * DD + cb) = w0;
            *(float2*)(C + (long)(r + 8) * DD + cb) = w1;
        }
    }
#undef LDG_KB
#undef STS_KB
}

// =====================================================================
// NN GEMM 64x64 (E/F precompute only): C = alpha*A@B + beta*Cin
// =====================================================================
__global__ void __launch_bounds__(256) gemm_nn(
    const float* __restrict__ A, int lda,
    const float* __restrict__ Bm, int ldb,
    float* __restrict__ C, int ldc,
    const float* __restrict__ Cin, float beta, float alpha, int K)
{
    int m0 = blockIdx.y << 6, n0 = blockIdx.x << 6;
    __shared__ float As[32][68];
    __shared__ float Bs[32][68];
    int tid = threadIdx.x;
    int tx = tid & 15, ty = tid >> 4;
    int lr = tid >> 3, lc = (tid & 7) << 2;
    int bkr = tid >> 4, bc = (tid & 15) << 2;
    const float* Ap = A  + (long)(m0 + lr) * lda + lc;
    const float* Bp = Bm + (long)bkr * ldb + n0 + bc;
    float acc[4][4] = {};
    for (int kb = 0; kb < K; kb += 32) {
        float4 a0 = *(const float4*)(Ap + kb);
        float4 a1 = *(const float4*)(Ap + kb + (long)32 * lda);
        float4 bv0 = *(const float4*)(Bp + (long)kb * ldb);
        float4 bv1 = *(const float4*)(Bp + (long)(kb + 16) * ldb);
        __syncthreads();
        As[lc+0][lr]=a0.x; As[lc+1][lr]=a0.y; As[lc+2][lr]=a0.z; As[lc+3][lr]=a0.w;
        As[lc+0][lr+32]=a1.x; As[lc+1][lr+32]=a1.y; As[lc+2][lr+32]=a1.z; As[lc+3][lr+32]=a1.w;
        *(float4*)(&Bs[bkr][bc])      = bv0;
        *(float4*)(&Bs[bkr + 16][bc]) = bv1;
        __syncthreads();
#pragma unroll
        for (int kk = 0; kk < 32; kk++) {
            float4 av = *(const float4*)(&As[kk][ty << 2]);
            float4 bv = *(const float4*)(&Bs[kk][tx << 2]);
            acc[0][0]+=av.x*bv.x; acc[0][1]+=av.x*bv.y; acc[0][2]+=av.x*bv.z; acc[0][3]+=av.x*bv.w;
            acc[1][0]+=av.y*bv.x; acc[1][1]+=av.y*bv.y; acc[1][2]+=av.y*bv.z; acc[1][3]+=av.y*bv.w;
            acc[2][0]+=av.z*bv.x; acc[2][1]+=av.z*bv.y; acc[2][2]+=av.z*bv.z; acc[2][3]+=av.z*bv.w;
            acc[3][0]+=av.w*bv.x; acc[3][1]+=av.w*bv.y; acc[3][2]+=av.w*bv.z; acc[3][3]+=av.w*bv.w;
        }
    }
#pragma unroll
    for (int i = 0; i < 4; i++) {
        long row = m0 + (ty << 2) + i;
#pragma unroll
        for (int j = 0; j < 4; j++) {
            int col = n0 + (tx << 2) + j;
            float v = alpha * acc[i][j];
            if (beta != 0.f) v += beta * Cin[row * ldc + col];
            C[row * ldc + col] = v;
        }
    }
}

// =====================================================================
// Pair: per (b,chunk) Skk = Kc@Kc^T, Aqk = Qc@Kc^T  (128x128, K=1024)
// =====================================================================
__global__ void __launch_bounds__(256) pair_kernel(
    const float* __restrict__ Km, const float* __restrict__ Qm,
    float* __restrict__ Skk, float* __restrict__ Aqk)
{
    int z = blockIdx.z;
    int rt = blockIdx.x, which = blockIdx.y;
    long co = ((long)(z / NCHK) * SS + (long)(z % NCHK) * CHK) * DD;
    const float* A  = (which ? Qm : Km) + co + (long)rt * 64 * DD;
    const float* Bm = Km + co;
    float* C = (which ? Aqk : Skk) + (long)z * CHK * CHK + (long)rt * 64 * CHK;

    __shared__ float SA[16][68];
    __shared__ float SB[16][132];
    int tid = threadIdx.x, tx = tid & 15, ty = tid >> 4;
    int ar = tid >> 2, ac = (tid & 3) << 2;
    const float* Ap = A  + (long)ar * DD + ac;
    const float* Bp = Bm + (long)ar * DD + ac;
    ull acc[4][4] = {};
    for (int kb = 0; kb < DD; kb += 16) {
        float4 a0 = *(const float4*)(Ap + kb);
        float4 b0 = *(const float4*)(Bp + kb);
        float4 b1 = *(const float4*)(Bp + kb + (long)64 * DD);
        __syncthreads();
        SA[ac+0][ar]=a0.x; SA[ac+1][ar]=a0.y; SA[ac+2][ar]=a0.z; SA[ac+3][ar]=a0.w;
        SB[ac+0][ar]=b0.x; SB[ac+1][ar]=b0.y; SB[ac+2][ar]=b0.z; SB[ac+3][ar]=b0.w;
        SB[ac+0][ar+64]=b1.x; SB[ac+1][ar+64]=b1.y; SB[ac+2][ar+64]=b1.z; SB[ac+3][ar+64]=b1.w;
        __syncthreads();
#pragma unroll
        for (int kk = 0; kk < 16; kk++) {
            float4 av = *(const float4*)&SA[kk][ty << 2];
            F4U B0, B1;
            B0.f = *(const float4*)&SB[kk][tx << 2];
            B1.f = *(const float4*)&SB[kk][64 + (tx << 2)];
            mm4x8(acc, av, B0, B1);
        }
    }
    int c0 = (tx << 2), c1 = c0 + 64;
#pragma unroll
    for (int i = 0; i < 4; i++) {
        long row = (ty << 2) + i;
        float2 p0 = unp(acc[i][0]), p1 = unp(acc[i][1]), p2 = unp(acc[i][2]), p3 = unp(acc[i][3]);
        *(float4*)(C + row * CHK + c0) = make_float4(p0.x, p0.y, p1.x, p1.y);
        *(float4*)(C + row * CHK + c1) = make_float4(p2.x, p2.y, p3.x, p3.y);
    }
}

// =====================================================================
// tinv64: invert diagonal 64x64 blocks of L = I + LAM*strict_lower(Skk+1)
// =====================================================================
__global__ void tinv64_kernel(const float* __restrict__ Skk, float* __restrict__ Ti)
{
    int z = blockIdx.y, db = blockIdx.x;
    const float* Ain = Skk + (long)z * CHK * CHK;
    float* T = Ti + (long)z * CHK * CHK;
    __shared__ float A[64][64];
    __shared__ float Ts[64][64];
    int j = threadIdx.x;
    int off = db * 64;
    for (int t = 0; t < 64; t++) A[t][j] = Ain[(long)(off + t) * CHK + off + j] + 1.0f;
    __syncthreads();
    for (int t = 0; t < 64; t++) {
        float v;
        if (t < j) v = 0.f;
        else if (t == j) v = 1.f;
        else {
            float ss = 0.f;
            for (int i = j; i < t; i++) ss += A[t][i] * Ts[i][j];
            v = -LAM * ss;
        }
        Ts[t][j] = v;
    }
    __syncthreads();
    for (int t = 0; t < 64; t++) T[(long)(off + t) * CHK + off + j] = Ts[t][j];
    if (db == 0)
        for (int t = 0; t < 64; t++) T[(long)t * CHK + 64 + j] = 0.f;
}

// =====================================================================
// tcomb: T21 = -T22 @ (LAM*(Skk21+1)) @ T11
// =====================================================================
__global__ void __launch_bounds__(256) tcomb_kernel(
    const float* __restrict__ Skk, float* __restrict__ Ti)
{
    long z = blockIdx.x;
    const float* Sk = Skk + z * CHK * CHK;
    float* T = Ti + z * CHK * CHK;
    __shared__ float T11[64 * 64];
    __shared__ float T22[64 * 64];
    __shared__ float X  [64 * 64];
    int tid = threadIdx.x;
    for (int i = tid; i < 4096; i += 256) {
        int r = i >> 6, c = i & 63;
        T11[i] = T[(long)r * CHK + c];
        T22[i] = T[(long)(64 + r) * CHK + 64 + c];
    }
    __syncthreads();
    int t = tid >> 2, jg = (tid & 3) << 4;
    float xr[16];
#pragma unroll
    for (int j = 0; j < 16; j++) xr[j] = 0.f;
    for (int i = 0; i < 64; i++) {
        float l = LAM * (Sk[(long)(64 + t) * CHK + i] + 1.0f);
#pragma unroll
        for (int j = 0; j < 16; j++) xr[j] += l * T11[(i << 6) + jg + j];
    }
#pragma unroll
    for (int j = 0; j < 16; j++) X[(t << 6) + jg + j] = xr[j];
    __syncthreads();
    float yr[16];
#pragma unroll
    for (int j = 0; j < 16; j++) yr[j] = 0.f;
    for (int i = 0; i < 64; i++) {
        float l = T22[(t << 6) + i];
#pragma unroll
        for (int j = 0; j < 16; j++) yr[j] += l * X[(i << 6) + jg + j];
    }
#pragma unroll
    for (int j = 0; j < 16; j++) T[(long)(64 + t) * CHK + jg + j] = -yr[j];
}

// =====================================================================
// Cross per chunk: grp0: Up = U_c - LAM*(Kc@M^T + s); grp1: out -= LR*(Qc@M^T + s)
// =====================================================================
__global__ void __launch_bounds__(256) cross_kernel(int chunk,
    const float* __restrict__ Km, const float* __restrict__ Qm,
    const float* __restrict__ U, const float* __restrict__ Mm,
    const float* __restrict__ s, float* __restrict__ Up, float* __restrict__ out)
{
    int b = blockIdx.z;
    int grp = blockIdx.y >> 1, rt = blockIdx.y & 1;
    int n0 = blockIdx.x << 7;
    long rowoff = ((long)b * SS + (long)chunk * CHK + rt * 64) * DD;
    const float* A; const float* Cin; float* Co; float alpha;
    if (grp == 0) { A = Km + rowoff; Cin = U + rowoff;   Co = Up + ((long)b * CHK + rt * 64) * DD; alpha = -LAM; }
    else          { A = Qm + rowoff; Cin = out + rowoff; Co = out + rowoff;                        alpha = -LRc; }
    const float* Bm = Mm + (long)b * DD * DD;
    const float* sb = s + (long)b * DD;

    __shared__ float SA[16][68];
    __shared__ float SB[16][132];
    int tid = threadIdx.x, tx = tid & 15, ty = tid >> 4;
    int ar = tid >> 2, ac = (tid & 3) << 2;
    const float* Ap = A  + (long)ar * DD + ac;
    const float* Bp = Bm + (long)(n0 + ar) * DD + ac;
    ull acc[4][4] = {};
    for (int kb = 0; kb < DD; kb += 16) {
        float4 a0 = *(const float4*)(Ap + kb);
        float4 b0 = *(const float4*)(Bp + kb);
        float4 b1 = *(const float4*)(Bp + kb + (long)64 * DD);
        __syncthreads();
        SA[ac+0][ar]=a0.x; SA[ac+1][ar]=a0.y; SA[ac+2][ar]=a0.z; SA[ac+3][ar]=a0.w;
        SB[ac+0][ar]=b0.x; SB[ac+1][ar]=b0.y; SB[ac+2][ar]=b0.z; SB[ac+3][ar]=b0.w;
        SB[ac+0][ar+64]=b1.x; SB[ac+1][ar+64]=b1.y; SB[ac+2][ar+64]=b1.z; SB[ac+3][ar+64]=b1.w;
        __syncthreads();
#pragma unroll
        for (int kk = 0; kk < 16; kk++) {
            float4 av = *(const float4*)&SA[kk][ty << 2];
            F4U B0, B1;
            B0.f = *(const float4*)&SB[kk][tx << 2];
            B1.f = *(const float4*)&SB[kk][64 + (tx << 2)];
            mm4x8(acc, av, B0, B1);
        }
    }
    int c0 = n0 + (tx << 2), c1 = c0 + 64;
    float s00 = sb[c0], s01 = sb[c0+1], s02 = sb[c0+2], s03 = sb[c0+3];
    float s10 = sb[c1], s11 = sb[c1+1], s12 = sb[c1+2], s13 = sb[c1+3];
#pragma unroll
    for (int i = 0; i < 4; i++) {
        long row = (ty << 2) + i;
        float2 p0 = unp(acc[i][0]), p1 = unp(acc[i][1]), p2 = unp(acc[i][2]), p3 = unp(acc[i][3]);
        float4 i0 = *(const float4*)(Cin + row * DD + c0);
        float4 i1 = *(const float4*)(Cin + row * DD + c1);
        float4 w0 = make_float4(i0.x + alpha*(p0.x+s00), i0.y + alpha*(p0.y+s01),
                                i0.z + alpha*(p1.x+s02), i0.w + alpha*(p1.y+s03));
        float4 w1 = make_float4(i1.x + alpha*(p2.x+s10), i1.y + alpha*(p2.y+s11),
                                i1.z + alpha*(p3.x+s12), i1.w + alpha*(p3.y+s13));
        *(float4*)(Co + row * DD + c0) = w0;
        *(float4*)(Co + row * DD + c1) = w1;
    }
}

// =====================================================================
// Solve: G = Ti @ Up  (128x1024, K=128)
// =====================================================================
__global__ void __launch_bounds__(256) solve_kernel(int chunk,
    const float* __restrict__ Ti, const float* __restrict__ Up, float* __restrict__ G)
{
    int b = blockIdx.z, rt = blockIdx.y, n0 = blockIdx.x << 7;
    const float* T = Ti + ((long)b * NCHK + chunk) * CHK * CHK + (long)rt * 64 * CHK;
    const float* B = Up + (long)b * CHK * DD;
    float* Gb = G + (long)b * CHK * DD + (long)rt * 64 * DD;
    __shared__ float SA[16][68];
    __shared__ float SB[16][132];
    int tid = threadIdx.x, tx = tid & 15, ty = tid >> 4;
    int ar = tid >> 2, ac = (tid & 3) << 2;
    int kr = tid >> 5, bc = (tid & 31) << 2;
    ull acc[4][4] = {};
    for (int kb = 0; kb < CHK; kb += 16) {
        float4 a0 = *(const float4*)(T + (long)ar * CHK + kb + ac);
        float4 b0 = *(const float4*)(B + (long)(kb + kr) * DD + n0 + bc);
        float4 b1 = *(const float4*)(B + (long)(kb + kr + 8) * DD + n0 + bc);
        __syncthreads();
        SA[ac+0][ar]=a0.x; SA[ac+1][ar]=a0.y; SA[ac+2][ar]=a0.z; SA[ac+3][ar]=a0.w;
        *(float4*)&SB[kr][bc] = b0;
        *(float4*)&SB[kr + 8][bc] = b1;
        __syncthreads();
#pragma unroll
        for (int kk = 0; kk < 16; kk++) {
            float4 av = *(const float4*)&SA[kk][ty << 2];
            F4U B0, B1;
            B0.f = *(const float4*)&SB[kk][tx << 2];
            B1.f = *(const float4*)&SB[kk][64 + (tx << 2)];
            mm4x8(acc, av, B0, B1);
        }
    }
    int c0 = n0 + (tx << 2), c1 = c0 + 64;
#pragma unroll
    for (int i = 0; i < 4; i++) {
        long row = (ty << 2) + i;
        float2 p0 = unp(acc[i][0]), p1 = unp(acc[i][1]), p2 = unp(acc[i][2]), p3 = unp(acc[i][3]);
        *(float4*)(Gb + row * DD + c0) = make_float4(p0.x, p0.y, p1.x, p1.y);
        *(float4*)(Gb + row * DD + c1) = make_float4(p2.x, p2.y, p3.x, p3.y);
    }
}

// =====================================================================
// Z2a: out_c -= LR * (masked(Aqk+1)) @ G   (128x1024, K=128)
// =====================================================================
__global__ void __launch_bounds__(256) z2a_kernel(int chunk,
    const float* __restrict__ Aqk, const float* __restrict__ G, float* __restrict__ out)
{
    int b = blockIdx.z, rt = blockIdx.y, n0 = blockIdx.x << 7;
    const float* Aq = Aqk + ((long)b * NCHK + chunk) * CHK * CHK;
    const float* B = G + (long)b * CHK * DD;
    float* O = out + ((long)b * SS + (long)chunk * CHK + rt * 64) * DD;
    __shared__ float SA[16][68];
    __shared__ float SB[16][132];
    int tid = threadIdx.x, tx = tid & 15, ty = tid >> 4;
    int ar = tid >> 2, ac = (tid & 3) << 2;
    int kr = tid >> 5, bc = (tid & 31) << 2;
    int tglob = rt * 64 + ar;
    ull acc[4][4] = {};
    for (int kb = 0; kb < CHK; kb += 16) {
        float4 a0 = *(const float4*)(Aq + (long)tglob * CHK + kb + ac);
        float4 b0 = *(const float4*)(B + (long)(kb + kr) * DD + n0 + bc);
        float4 b1 = *(const float4*)(B + (long)(kb + kr + 8) * DD + n0 + bc);
        __syncthreads();
        int i0 = kb + ac;
        SA[ac+0][ar] = (i0+0 <= tglob) ? a0.x + 1.0f : 0.f;
        SA[ac+1][ar] = (i0+1 <= tglob) ? a0.y + 1.0f : 0.f;
        SA[ac+2][ar] = (i0+2 <= tglob) ? a0.z + 1.0f : 0.f;
        SA[ac+3][ar] = (i0+3 <= tglob) ? a0.w + 1.0f : 0.f;
        *(float4*)&SB[kr][bc] = b0;
        *(float4*)&SB[kr + 8][bc] = b1;
        __syncthreads();
#pragma unroll
        for (int kk = 0; kk < 16; kk++) {
            float4 av = *(const float4*)&SA[kk][ty << 2];
            F4U B0, B1;
            B0.f = *(const float4*)&SB[kk][tx << 2];
            B1.f = *(const float4*)&SB[kk][64 + (tx << 2)];
            mm4x8(acc, av, B0, B1);
        }
    }
    int c0 = n0 + (tx << 2), c1 = c0 + 64;
#pragma unroll
    for (int i = 0; i < 4; i++) {
        long row = (ty << 2) + i;
        float2 p0 = unp(acc[i][0]), p1 = unp(acc[i][1]), p2 = unp(acc[i][2]), p3 = unp(acc[i][3]);
        float4 o0 = *(const float4*)(O + row * DD + c0);
        float4 o1 = *(const float4*)(O + row * DD + c1);
        o0.x -= LRc * p0.x; o0.y -= LRc * p0.y; o0.z -= LRc * p1.x; o0.w -= LRc * p1.y;
        o1.x -= LRc * p2.x; o1.y -= LRc * p2.y; o1.z -= LRc * p3.x; o1.w -= LRc * p3.y;
        *(float4*)(O + row * DD + c0) = o0;
        *(float4*)(O + row * DD + c1) = o1;
    }
}

// =====================================================================
// Z2b: M += G^T @ Kc (1024x1024, K=128); plus colsum(G) into s.
// =====================================================================
__global__ void __launch_bounds__(256, 2) z2b_kernel(int chunk,
    const float* __restrict__ G, const float* __restrict__ Km,
    float* __restrict__ Mm, float* __restrict__ s)
{
    int b = blockIdx.z;
    const float* Ga = G + (long)b * CHK * DD;
    if (blockIdx.y == 8) {
        if (blockIdx.x >= 4) return;
        int col = (blockIdx.x << 8) + threadIdx.x;
        float t = 0.f;
#pragma unroll 8
        for (int r = 0; r < CHK; r++) t += Ga[(long)r * DD + col];
        s[(long)b * DD + col] += t;
        return;
    }
    int e0 = blockIdx.x << 7, d0 = blockIdx.y << 7;
    const float* Kc = Km + ((long)b * SS + (long)chunk * CHK) * DD;
    float* Mb = Mm + (long)b * DD * DD;
    __shared__ float SA[16][132];
    __shared__ float SB[16][132];
    int tid = threadIdx.x, tx = tid & 15, ty = tid >> 4;
    int kr = tid >> 5, bc = (tid & 31) << 2;
    ull acc[8][4] = {};
    for (int kb = 0; kb < CHK; kb += 16) {
        float4 a0 = *(const float4*)(Ga + (long)(kb + kr) * DD + e0 + bc);
        float4 a1 = *(const float4*)(Ga + (long)(kb + kr + 8) * DD + e0 + bc);
        float4 b0 = *(const float4*)(Kc + (long)(kb + kr) * DD + d0 + bc);
        float4 b1 = *(const float4*)(Kc + (long)(kb + kr + 8) * DD + d0 + bc);
        __syncthreads();
        *(float4*)&SA[kr][bc] = a0; *(float4*)&SA[kr + 8][bc] = a1;
        *(float4*)&SB[kr][bc] = b0; *(float4*)&SB[kr + 8][bc] = b1;
        __syncthreads();
#pragma unroll
        for (int kk = 0; kk < 16; kk++) {
            float4 av0 = *(const float4*)&SA[kk][ty << 2];
            float4 av1 = *(const float4*)&SA[kk][64 + (ty << 2)];
            F4U B0, B1;
            B0.f = *(const float4*)&SB[kk][tx << 2];
            B1.f = *(const float4*)&SB[kk][64 + (tx << 2)];
            mm4x8(&acc[0], av0, B0, B1);
            mm4x8(&acc[4], av1, B0, B1);
        }
    }
    int c0 = d0 + (tx << 2), c1 = c0 + 64;
#pragma unroll
    for (int i = 0; i < 8; i++) {
        long row = e0 + ((i < 4) ? ((ty << 2) + i) : (64 + (ty << 2) + i - 4));
        float2 p0 = unp(acc[i][0]), p1 = unp(acc[i][1]), p2 = unp(acc[i][2]), p3 = unp(acc[i][3]);
        float4 m0 = *(const float4*)(Mb + row * DD + c0);
        float4 m1 = *(const float4*)(Mb + row * DD + c1);
        m0.x += p0.x; m0.y += p0.y; m0.z += p1.x; m0.w += p1.y;
        m1.x += p2.x; m1.y += p2.y; m1.z += p3.x; m1.w += p3.y;
        *(float4*)(Mb + row * DD + c0) = m0;
        *(float4*)(Mb + row * DD + c1) = m1;
    }
}

__global__ void zero_kernel(float* __restrict__ p, long n)
{
    long i = (long)blockIdx.x * blockDim.x + threadIdx.x;
    long stride = (long)gridDim.x * blockDim.x;
    for (; i < n; i += stride) p[i] = 0.f;
}

// =====================================================================
// host launcher
// =====================================================================
extern "C" void kernel_launch(void* const* d_in, const int* in_sizes, int n_in,
                              void* d_out, int out_size)
{
    (void)in_sizes; (void)n_in; (void)out_size;
    const float* in_seq = (const float*)d_in[0];
    const float* thK = (const float*)d_in[1];
    const float* thV = (const float*)d_in[2];
    const float* thQ = (const float*)d_in[3];
    const float* W0  = (const float*)d_in[4];
    const float* b0  = (const float*)d_in[5];
    float* out = (float*)d_out;

    float *pK, *pQ, *pU, *pM, *ps, *pG, *pUp, *pSkk, *pAqk, *pTi, *pE, *pF;
    __nv_bfloat16 *pX2, *pWK, *pWQ, *pWE, *pWF;
    cudaGetSymbolAddress((void**)&pK, g_K);
    cudaGetSymbolAddress((void**)&pQ, g_Q);
    cudaGetSymbolAddress((void**)&pU, g_U);
    cudaGetSymbolAddress((void**)&pM, g_M);
    cudaGetSymbolAddress((void**)&ps, g_s);
    cudaGetSymbolAddress((void**)&pG, g_G);
    cudaGetSymbolAddress((void**)&pUp, g_Up);
    cudaGetSymbolAddress((void**)&pSkk, g_Skk);
    cudaGetSymbolAddress((void**)&pAqk, g_Aqk);
    cudaGetSymbolAddress((void**)&pTi, g_Ti);
    cudaGetSymbolAddress((void**)&pE, g_E);
    cudaGetSymbolAddress((void**)&pF, g_F);
    cudaGetSymbolAddress((void**)&pX2, g_X2);
    cudaGetSymbolAddress((void**)&pWK, g_WK);
    cudaGetSymbolAddress((void**)&pWQ, g_WQ);
    cudaGetSymbolAddress((void**)&pWE, g_WE);
    cudaGetSymbolAddress((void**)&pWF, g_WF);

    // E = W0@thK - thV, F = W0@thQ  (fp32)
    dim3 g16(16, 16, 1);
    gemm_nn<<<g16, 256>>>(W0, DD, thK, DD, pE, DD, thV, -1.f, 1.f, DD);
    gemm_nn<<<g16, 256>>>(W0, DD, thQ, DD, pF, DD, nullptr, 0.f, 1.f, DD);

    // split-bf16 conversions
    cvt_a_kernel<<<8192, 256>>>(in_seq, pX2, (long)BB * SS * DD);
    cvt_b_kernel<<<1024, 256>>>(thK, pWK, (long)DD * DD);
    cvt_b_kernel<<<1024, 256>>>(thQ, pWQ, (long)DD * DD);
    cvt_b_kernel<<<1024, 256>>>(pE,  pWE, (long)DD * DD);
    cvt_b_kernel<<<1024, 256>>>(pF,  pWF, (long)DD * DD);

    // big projections via HMMA tensor cores
    dim3 gm(DD / 128, (BB * SS) / 128, 1);
    hmma_nt<<<gm, 256>>>(pX2, pWK, pK, nullptr, 1.f);
    hmma_nt<<<gm, 256>>>(pX2, pWQ, pQ, nullptr, 1.f);
    hmma_nt<<<gm, 256>>>(pX2, pWE, pU, b0, GSC);
    hmma_nt<<<gm, 256>>>(pX2, pWF, out, b0, 1.f);

    // Gram matrices + triangular inverses
    pair_kernel<<<dim3(2, 2, BB * NCHK), 256>>>(pK, pQ, pSkk, pAqk);
    tinv64_kernel<<<dim3(2, BB * NCHK), 64>>>(pSkk, pTi);
    tcomb_kernel<<<BB * NCHK, 256>>>(pSkk, pTi);

    // zero state
    zero_kernel<<<512, 256>>>(pM, (long)BB * DD * DD);
    zero_kernel<<<8, 256>>>(ps, (long)BB * DD);

    // chunk loop (SIMT)
    for (int c = 0; c < NCHK; c++) {
        cross_kernel<<<dim3(8, 4, BB), 256>>>(c, pK, pQ, pU, pM, ps, pUp, out);
        solve_kernel<<<dim3(8, 2, BB), 256>>>(c, pTi, pUp, pG);
        z2a_kernel<<<dim3(8, 2, BB), 256>>>(c, pAqk, pG, out);
        z2b_kernel<<<dim3(8, 9, BB), 256>>>(c, pG, pK, pM, ps);
    }
}

// round 11
// speedup vs baseline: 1.6258x; 1.0032x over previous
#include <cuda_runtime.h>
#include <cuda_bf16.h>
#include <cstdint>

#define BB   8
#define SS   2048
#define DD   1024
#define CHK  128
#define NCHK (SS / CHK)              // 16
#define LRc  0.01f
#define LAM  (2.0f * 0.01f / 1024.0f)
#define GSC  (2.0f / 1024.0f)
#define K3   3072                    // packed split-bf16 K
#define NKB  (K3 / 32)               // 96

typedef unsigned long long ull;
typedef __nv_bfloat16 bf16;

// ---------------- packed f32x2 helpers (SIMT kernels) ----------------
__device__ __forceinline__ ull dupf(float x) {
    ull r; asm("mov.b64 %0, {%1, %1};" : "=l"(r) : "f"(x)); return r;
}
__device__ __forceinline__ void ffma2(ull& d, ull a, ull b) {
    asm("fma.rn.f32x2 %0, %1, %2, %0;" : "+l"(d) : "l"(a), "l"(b));
}
__device__ __forceinline__ float2 unp(ull v) {
    float lo, hi; asm("mov.b64 {%0, %1}, %2;" : "=f"(lo), "=f"(hi) : "l"(v));
    return make_float2(lo, hi);
}
union F4U { float4 f; ull u[2]; };

__device__ __forceinline__ void mm4x8(ull acc[][4], float4 av, const F4U& B0, const F4U& B1) {
    ull a0 = dupf(av.x), a1 = dupf(av.y), a2 = dupf(av.z), a3 = dupf(av.w);
    ffma2(acc[0][0], a0, B0.u[0]); ffma2(acc[0][1], a0, B0.u[1]); ffma2(acc[0][2], a0, B1.u[0]); ffma2(acc[0][3], a0, B1.u[1]);
    ffma2(acc[1][0], a1, B0.u[0]); ffma2(acc[1][1], a1, B0.u[1]); ffma2(acc[1][2], a1, B1.u[0]); ffma2(acc[1][3], a1, B1.u[1]);
    ffma2(acc[2][0], a2, B0.u[0]); ffma2(acc[2][1], a2, B0.u[1]); ffma2(acc[2][2], a2, B1.u[0]); ffma2(acc[2][3], a2, B1.u[1]);
    ffma2(acc[3][0], a3, B0.u[0]); ffma2(acc[3][1], a3, B0.u[1]); ffma2(acc[3][2], a3, B1.u[0]); ffma2(acc[3][3], a3, B1.u[1]);
}

// ---------------- HMMA helpers ----------------
__device__ __forceinline__ uint32_t smem_u32(const void* p) {
    uint32_t a;
    asm("{ .reg .u64 t; cvta.to.shared.u64 t, %1; cvt.u32.u64 %0, t; }" : "=r"(a) : "l"(p));
    return a;
}
__device__ __forceinline__ void ldm4(uint32_t& r0, uint32_t& r1, uint32_t& r2, uint32_t& r3, uint32_t addr) {
    asm volatile("ldmatrix.sync.aligned.m8n8.x4.shared.b16 {%0,%1,%2,%3}, [%4];"
        : "=r"(r0), "=r"(r1), "=r"(r2), "=r"(r3) : "r"(addr));
}
__device__ __forceinline__ void mma16816(float* d, const uint32_t* a, const uint32_t* b) {
    asm volatile("mma.sync.aligned.m16n8k16.row.col.f32.bf16.bf16.f32 "
        "{%0,%1,%2,%3}, {%4,%5,%6,%7}, {%8,%9}, {%0,%1,%2,%3};"
        : "+f"(d[0]), "+f"(d[1]), "+f"(d[2]), "+f"(d[3])
        : "r"(a[0]), "r"(a[1]), "r"(a[2]), "r"(a[3]), "r"(b[0]), "r"(b[1]));
}

#define SROW 40
#define STILE (128 * SROW)

// shared 128x128 NT mainloop: acc[mt][nt][4]; A rows m0.., B rows n0.. pre-offset by caller
__device__ __forceinline__ void hmma_mainloop(
    const bf16* __restrict__ Abase, long lda,
    const bf16* __restrict__ Bbase, long ldb, int nkb,
    bf16 (*SA)[STILE], bf16 (*SB)[STILE],
    float acc[4][4][4], int tid)
{
    const int lane = tid & 31, wid = tid >> 5;
    const int wr = wid >> 2, wc = wid & 3;
    const int lr = tid >> 1, lc = (tid & 1) << 4;
    const bf16* Ap = Abase + (long)lr * lda + lc;
    const bf16* Bp = Bbase + (long)lr * ldb + lc;
    const uint32_t sa0 = smem_u32(SA), sb0 = smem_u32(SB);
    const uint32_t a_ro = (uint32_t)(wr * 64 + (lane & 15)) * (SROW * 2) + ((lane >> 4) << 3) * 2;
    const uint32_t b_ro = (uint32_t)(wc * 32 + ((lane >> 4) << 3) + (lane & 7)) * (SROW * 2)
                        + (((lane >> 3) & 1) << 3) * 2;
    uint4 ra0, ra1, rb0, rb1;
#define LDG_KB(c) do { \
    ra0 = *(const uint4*)(Ap + (c) * 32); \
    ra1 = *(const uint4*)(Ap + (c) * 32 + 8); \
    rb0 = *(const uint4*)(Bp + (c) * 32); \
    rb1 = *(const uint4*)(Bp + (c) * 32 + 8); } while (0)
#define STS_KB(s) do { \
    *(uint4*)&SA[s][lr * SROW + lc] = ra0; \
    *(uint4*)&SA[s][lr * SROW + lc + 8] = ra1; \
    *(uint4*)&SB[s][lr * SROW + lc] = rb0; \
    *(uint4*)&SB[s][lr * SROW + lc + 8] = rb1; } while (0)
    LDG_KB(0);
    for (int c = 0; c < nkb; c++) {
        int s = c & 1;
        STS_KB(s);
        if (c + 1 < nkb) LDG_KB(c + 1);
        __syncthreads();
        uint32_t abase = sa0 + (uint32_t)s * (STILE * 2) + a_ro;
        uint32_t bbase = sb0 + (uint32_t)s * (STILE * 2) + b_ro;
#pragma unroll
        for (int kk = 0; kk < 2; kk++) {
            uint32_t af[4][4], bfr[4][2];
#pragma unroll
            for (int mt = 0; mt < 4; mt++)
                ldm4(af[mt][0], af[mt][1], af[mt][2], af[mt][3],
                     abase + (uint32_t)(mt * 16) * (SROW * 2) + kk * 32);
#pragma unroll
            for (int p = 0; p < 2; p++) {
                uint32_t t0, t1, t2, t3;
                ldm4(t0, t1, t2, t3, bbase + (uint32_t)(p * 16) * (SROW * 2) + kk * 32);
                bfr[2 * p][0] = t0; bfr[2 * p][1] = t1;
                bfr[2 * p + 1][0] = t2; bfr[2 * p + 1][1] = t3;
            }
#pragma unroll
            for (int mt = 0; mt < 4; mt++)
#pragma unroll
                for (int nt = 0; nt < 4; nt++)
                    mma16816(acc[mt][nt], af[mt], bfr[nt]);
        }
        __syncthreads();
    }
#undef LDG_KB
#undef STS_KB
}

// ---------------- static device scratch ----------------
__device__ float g_K [BB * SS * DD];
__device__ float g_Q [BB * SS * DD];
__device__ float g_U [BB * SS * DD];
__device__ float g_s [BB * DD];
__device__ float g_G [BB * CHK * DD];
__device__ float g_Up[BB * CHK * DD];
__device__ float g_Skk[BB * NCHK * CHK * CHK];
__device__ float g_Aqk[BB * NCHK * CHK * CHK];
__device__ float g_Ti [BB * NCHK * CHK * CHK];
__device__ float g_E [DD * DD];
__device__ float g_F [DD * DD];
__device__ bf16 g_X2 [(long)BB * SS * K3];   // A-layout [hi|hi|lo]
__device__ bf16 g_WK [DD * K3];              // B-layout [hi|lo|hi]
__device__ bf16 g_WQ [DD * K3];
__device__ bf16 g_WE [DD * K3];
__device__ bf16 g_WF [DD * K3];
__device__ bf16 g_K2a[(long)BB * SS * K3];   // K as A operand
__device__ bf16 g_Q2a[(long)BB * SS * K3];   // Q as A operand
__device__ bf16 g_K2b[(long)BB * SS * K3];   // K as B operand (pair)
__device__ bf16 g_Kt2[(long)BB * NCHK * DD * 384]; // per-chunk K^T, B-layout along t
__device__ bf16 g_M2 [(long)BB * DD * K3];   // state, B-layout along d
__device__ bf16 g_Gt2[(long)BB * DD * 384];  // per-chunk G^T, A-layout along t

// =====================================================================
// split-bf16 conversions
// =====================================================================
__global__ void cvt_a_kernel(const float* __restrict__ s, bf16* __restrict__ d, long n)
{
    for (long i = (long)blockIdx.x * blockDim.x + threadIdx.x; i < n; i += (long)gridDim.x * blockDim.x) {
        long r = i >> 10; int c = (int)(i & 1023);
        float x = s[i];
        bf16 h = __float2bfloat16(x);
        bf16 l = __float2bfloat16(x - __bfloat162float(h));
        bf16* row = d + r * K3;
        row[c] = h; row[1024 + c] = h; row[2048 + c] = l;
    }
}
__global__ void cvt_b_kernel(const float* __restrict__ s, bf16* __restrict__ d, long n)
{
    for (long i = (long)blockIdx.x * blockDim.x + threadIdx.x; i < n; i += (long)gridDim.x * blockDim.x) {
        long r = i >> 10; int c = (int)(i & 1023);
        float x = s[i];
        bf16 h = __float2bfloat16(x);
        bf16 l = __float2bfloat16(x - __bfloat162float(h));
        bf16* row = d + r * K3;
        row[c] = h; row[1024 + c] = l; row[2048 + c] = h;
    }
}

// kt: K[t,d] per chunk -> Kt2[d, 384] B-layout along t
__global__ void kt_kernel(const float* __restrict__ K, bf16* __restrict__ Kt2)
{
    int bc = blockIdx.y;          // b*16+c
    int d0 = blockIdx.x << 5;     // 32-col block
    __shared__ float T[128][33];
    int tid = threadIdx.x;
    int b = bc >> 4, c = bc & 15;
    const float* Kc = K + ((long)b * SS + (long)c * CHK) * DD;
#pragma unroll
    for (int rep = 0; rep < 16; rep++) {
        int idx = rep * 256 + tid;
        int t = idx >> 5, dd = idx & 31;
        T[t][dd] = Kc[(long)t * DD + d0 + dd];
    }
    __syncthreads();
    bf16* Ob = Kt2 + ((long)bc * DD + d0) * 384;
#pragma unroll
    for (int rep = 0; rep < 16; rep++) {
        int idx = rep * 256 + tid;
        int dl = idx >> 7, t = idx & 127;
        float v = T[t][dl];
        bf16 h = __float2bfloat16(v);
        bf16 l = __float2bfloat16(v - __bfloat162float(h));
        bf16* row = Ob + (long)dl * 384;
        row[t] = h; row[128 + t] = l; row[256 + t] = h;
    }
}

// gt: G[t,n] per chunk -> Gt2[n, 384] A-layout along t
__global__ void gt_kernel(const float* __restrict__ G, bf16* __restrict__ Gt2)
{
    int b = blockIdx.y;
    int n0 = blockIdx.x << 5;
    __shared__ float T[128][33];
    int tid = threadIdx.x;
    const float* Gb = G + (long)b * CHK * DD;
#pragma unroll
    for (int rep = 0; rep < 16; rep++) {
        int idx = rep * 256 + tid;
        int t = idx >> 5, dn = idx & 31;
        T[t][dn] = Gb[(long)t * DD + n0 + dn];
    }
    __syncthreads();
    bf16* Ob = Gt2 + ((long)b * DD + n0) * 384;
#pragma unroll
    for (int rep = 0; rep < 16; rep++) {
        int idx = rep * 256 + tid;
        int nl = idx >> 7, t = idx & 127;
        float v = T[t][nl];
        bf16 h = __float2bfloat16(v);
        bf16 l = __float2bfloat16(v - __bfloat162float(h));
        bf16* row = Ob + (long)nl * 384;
        row[t] = h; row[128 + t] = h; row[256 + t] = l;
    }
}

// =====================================================================
// HMMA projection GEMM (4 big projections): C = alpha*(A@B^T + bias)
// =====================================================================
__global__ void __launch_bounds__(256) hmma_proj(
    const bf16* __restrict__ A2, const bf16* __restrict__ B2,
    float* __restrict__ C, const float* __restrict__ bias, float alpha)
{
    __shared__ bf16 SA[2][STILE];
    __shared__ bf16 SB[2][STILE];
    const int tid = threadIdx.x, lane = tid & 31, wid = tid >> 5;
    const int wr = wid >> 2, wc = wid & 3;
    const int m0 = blockIdx.y << 7, n0 = blockIdx.x << 7;
    float acc[4][4][4];
#pragma unroll
    for (int i = 0; i < 4; i++)
#pragma unroll
        for (int j = 0; j < 4; j++)
#pragma unroll
            for (int k = 0; k < 4; k++) acc[i][j][k] = 0.f;
    hmma_mainloop(A2 + (long)m0 * K3, K3, B2 + (long)n0 * K3, K3, NKB, SA, SB, acc, tid);
#pragma unroll
    for (int mt = 0; mt < 4; mt++) {
        int r = m0 + wr * 64 + mt * 16 + (lane >> 2);
#pragma unroll
        for (int nt = 0; nt < 4; nt++) {
            int cb = n0 + wc * 32 + nt * 8 + ((lane & 3) << 1);
            float b0v = bias ? bias[cb] : 0.f, b1v = bias ? bias[cb + 1] : 0.f;
            *(float2*)(C + (long)r * DD + cb) =
                make_float2(alpha * (acc[mt][nt][0] + b0v), alpha * (acc[mt][nt][1] + b1v));
            *(float2*)(C + (long)(r + 8) * DD + cb) =
                make_float2(alpha * (acc[mt][nt][2] + b0v), alpha * (acc[mt][nt][3] + b1v));
        }
    }
}

// =====================================================================
// HMMA pair: Skk = Kc@Kc^T, Aqk = Qc@Kc^T per (b,chunk), K=K3
// =====================================================================
__global__ void __launch_bounds__(256) hmma_pair(
    const bf16* __restrict__ K2a, const bf16* __restrict__ Q2a, const bf16* __restrict__ K2b,
    float* __restrict__ Skk, float* __restrict__ Aqk)
{
    __shared__ bf16 SA[2][STILE];
    __shared__ bf16 SB[2][STILE];
    const int tid = threadIdx.x, lane = tid & 31, wid = tid >> 5;
    const int wr = wid >> 2, wc = wid & 3;
    int z = blockIdx.y, which = blockIdx.x;
    int b = z >> 4, c = z & 15;
    long rowoff = ((long)b * SS + (long)c * CHK) * K3;
    const bf16* A = (which ? Q2a : K2a) + rowoff;
    const bf16* B = K2b + rowoff;
    float* C = (which ? Aqk : Skk) + (long)z * CHK * CHK;
    float acc[4][4][4];
#pragma unroll
    for (int i = 0; i < 4; i++)
#pragma unroll
        for (int j = 0; j < 4; j++)
#pragma unroll
            for (int k = 0; k < 4; k++) acc[i][j][k] = 0.f;
    hmma_mainloop(A, K3, B, K3, NKB, SA, SB, acc, tid);
#pragma unroll
    for (int mt = 0; mt < 4; mt++) {
        int r = wr * 64 + mt * 16 + (lane >> 2);
#pragma unroll
        for (int nt = 0; nt < 4; nt++) {
            int cb = wc * 32 + nt * 8 + ((lane & 3) << 1);
            *(float2*)(C + (long)r * CHK + cb) = make_float2(acc[mt][nt][0], acc[mt][nt][1]);
            *(float2*)(C + (long)(r + 8) * CHK + cb) = make_float2(acc[mt][nt][2], acc[mt][nt][3]);
        }
    }
}

// =====================================================================
// HMMA cross: grp0: Up = U_c - LAM*(Kc@M^T + s); grp1: out -= LR*(Qc@M^T + s)
// =====================================================================
__global__ void __launch_bounds__(256) hmma_cross(int chunk,
    const bf16* __restrict__ K2a, const bf16* __restrict__ Q2a, const bf16* __restrict__ M2,
    const float* __restrict__ U, const float* __restrict__ s,
    float* __restrict__ Up, float* __restrict__ out)
{
    __shared__ bf16 SA[2][STILE];
    __shared__ bf16 SB[2][STILE];
    const int tid = threadIdx.x, lane = tid & 31, wid = tid >> 5;
    const int wr = wid >> 2, wc = wid & 3;
    int b = blockIdx.z, grp = blockIdx.y, n0 = blockIdx.x << 7;
    long crow = (long)b * SS + (long)chunk * CHK;
    const bf16* A = (grp ? Q2a : K2a) + crow * K3;
    const bf16* B = M2 + ((long)b * DD + n0) * K3;
    const float* Cin; float* Co; float alpha;
    if (grp == 0) { Cin = U + crow * DD; Co = Up + (long)b * CHK * DD; alpha = -LAM; }
    else          { Cin = out + crow * DD; Co = out + crow * DD;       alpha = -LRc; }
    const float* sb = s + (long)b * DD;
    float acc[4][4][4];
#pragma unroll
    for (int i = 0; i < 4; i++)
#pragma unroll
        for (int j = 0; j < 4; j++)
#pragma unroll
            for (int k = 0; k < 4; k++) acc[i][j][k] = 0.f;
    hmma_mainloop(A, K3, B, K3, NKB, SA, SB, acc, tid);
#pragma unroll
    for (int mt = 0; mt < 4; mt++) {
        int r = wr * 64 + mt * 16 + (lane >> 2);
#pragma unroll
        for (int nt = 0; nt < 4; nt++) {
            int cb = n0 + wc * 32 + nt * 8 + ((lane & 3) << 1);
            float s0 = sb[cb], s1 = sb[cb + 1];
            float2 i0 = *(const float2*)(Cin + (long)r * DD + cb);
            float2 i1 = *(const float2*)(Cin + (long)(r + 8) * DD + cb);
            *(float2*)(Co + (long)r * DD + cb) =
                make_float2(i0.x + alpha * (acc[mt][nt][0] + s0), i0.y + alpha * (acc[mt][nt][1] + s1));
            *(float2*)(Co + (long)(r + 8) * DD + cb) =
                make_float2(i1.x + alpha * (acc[mt][nt][2] + s0), i1.y + alpha * (acc[mt][nt][3] + s1));
        }
    }
}

// =====================================================================
// HMMA z2b: M2 += Gt2 @ Kt2^T (per chunk, K=384), split-bf16 state update
// =====================================================================
__device__ __forceinline__ void m2_update(bf16* M2b, long e, int d, float a0, float a1)
{
    long base = e * K3 + d;
    __nv_bfloat162 hv = *(__nv_bfloat162*)(M2b + base);
    __nv_bfloat162 lv = *(__nv_bfloat162*)(M2b + base + 1024);
    float m0 = __bfloat162float(hv.x) + __bfloat162float(lv.x) + a0;
    float m1 = __bfloat162float(hv.y) + __bfloat162float(lv.y) + a1;
    bf16 h0 = __float2bfloat16(m0), h1 = __float2bfloat16(m1);
    bf16 l0 = __float2bfloat16(m0 - __bfloat162float(h0));
    bf16 l1 = __float2bfloat16(m1 - __bfloat162float(h1));
    __nv_bfloat162 hh; hh.x = h0; hh.y = h1;
    __nv_bfloat162 ll; ll.x = l0; ll.y = l1;
    *(__nv_bfloat162*)(M2b + base) = hh;
    *(__nv_bfloat162*)(M2b + base + 1024) = ll;
    *(__nv_bfloat162*)(M2b + base + 2048) = hh;
}

__global__ void __launch_bounds__(256) hmma_z2b(int chunk,
    const bf16* __restrict__ Gt2, const bf16* __restrict__ Kt2, bf16* __restrict__ M2)
{
    __shared__ bf16 SA[2][STILE];
    __shared__ bf16 SB[2][STILE];
    const int tid = threadIdx.x, lane = tid & 31, wid = tid >> 5;
    const int wr = wid >> 2, wc = wid & 3;
    int b = blockIdx.z, d0 = blockIdx.y << 7, e0 = blockIdx.x << 7;
    const bf16* A = Gt2 + ((long)b * DD + e0) * 384;
    const bf16* B = Kt2 + (((long)(b * NCHK + chunk)) * DD + d0) * 384;
    bf16* M2b = M2 + (long)b * DD * K3;
    float acc[4][4][4];
#pragma unroll
    for (int i = 0; i < 4; i++)
#pragma unroll
        for (int j = 0; j < 4; j++)
#pragma unroll
            for (int k = 0; k < 4; k++) acc[i][j][k] = 0.f;
    hmma_mainloop(A, 384, B, 384, 12, SA, SB, acc, tid);
#pragma unroll
    for (int mt = 0; mt < 4; mt++) {
        long e = e0 + wr * 64 + mt * 16 + (lane >> 2);
#pragma unroll
        for (int nt = 0; nt < 4; nt++) {
            int d = d0 + wc * 32 + nt * 8 + ((lane & 3) << 1);
            m2_update(M2b, e, d, acc[mt][nt][0], acc[mt][nt][1]);
            m2_update(M2b, e + 8, d, acc[mt][nt][2], acc[mt][nt][3]);
        }
    }
}

// colsum of G into s
__global__ void colsum_kernel(const float* __restrict__ G, float* __restrict__ s)
{
    int b = blockIdx.y;
    int col = (blockIdx.x << 8) + threadIdx.x;
    const float* Ga = G + (long)b * CHK * DD;
    float t = 0.f;
#pragma unroll 8
    for (int r = 0; r < CHK; r++) t += Ga[(long)r * DD + col];
    s[(long)b * DD + col] += t;
}

// =====================================================================
// NN GEMM 64x64 (E/F precompute only)
// =====================================================================
__global__ void __launch_bounds__(256) gemm_nn(
    const float* __restrict__ A, int lda,
    const float* __restrict__ Bm, int ldb,
    float* __restrict__ C, int ldc,
    const float* __restrict__ Cin, float beta, float alpha, int K)
{
    int m0 = blockIdx.y << 6, n0 = blockIdx.x << 6;
    __shared__ float As[32][68];
    __shared__ float Bs[32][68];
    int tid = threadIdx.x;
    int tx = tid & 15, ty = tid >> 4;
    int lr = tid >> 3, lc = (tid & 7) << 2;
    int bkr = tid >> 4, bc = (tid & 15) << 2;
    const float* Ap = A  + (long)(m0 + lr) * lda + lc;
    const float* Bp = Bm + (long)bkr * ldb + n0 + bc;
    float acc[4][4] = {};
    for (int kb = 0; kb < K; kb += 32) {
        float4 a0 = *(const float4*)(Ap + kb);
        float4 a1 = *(const float4*)(Ap + kb + (long)32 * lda);
        float4 bv0 = *(const float4*)(Bp + (long)kb * ldb);
        float4 bv1 = *(const float4*)(Bp + (long)(kb + 16) * ldb);
        __syncthreads();
        As[lc+0][lr]=a0.x; As[lc+1][lr]=a0.y; As[lc+2][lr]=a0.z; As[lc+3][lr]=a0.w;
        As[lc+0][lr+32]=a1.x; As[lc+1][lr+32]=a1.y; As[lc+2][lr+32]=a1.z; As[lc+3][lr+32]=a1.w;
        *(float4*)(&Bs[bkr][bc])      = bv0;
        *(float4*)(&Bs[bkr + 16][bc]) = bv1;
        __syncthreads();
#pragma unroll
        for (int kk = 0; kk < 32; kk++) {
            float4 av = *(const float4*)(&As[kk][ty << 2]);
            float4 bv = *(const float4*)(&Bs[kk][tx << 2]);
            acc[0][0]+=av.x*bv.x; acc[0][1]+=av.x*bv.y; acc[0][2]+=av.x*bv.z; acc[0][3]+=av.x*bv.w;
            acc[1][0]+=av.y*bv.x; acc[1][1]+=av.y*bv.y; acc[1][2]+=av.y*bv.z; acc[1][3]+=av.y*bv.w;
            acc[2][0]+=av.z*bv.x; acc[2][1]+=av.z*bv.y; acc[2][2]+=av.z*bv.z; acc[2][3]+=av.z*bv.w;
            acc[3][0]+=av.w*bv.x; acc[3][1]+=av.w*bv.y; acc[3][2]+=av.w*bv.z; acc[3][3]+=av.w*bv.w;
        }
    }
#pragma unroll
    for (int i = 0; i < 4; i++) {
        long row = m0 + (ty << 2) + i;
#pragma unroll
        for (int j = 0; j < 4; j++) {
            int col = n0 + (tx << 2) + j;
            float v = alpha * acc[i][j];
            if (beta != 0.f) v += beta * Cin[row * ldc + col];
            C[row * ldc + col] = v;
        }
    }
}

// =====================================================================
// tinv64 + tcomb (128x128 unit-lower-triangular inverse, blockwise)
// =====================================================================
__global__ void tinv64_kernel(const float* __restrict__ Skk, float* __restrict__ Ti)
{
    int z = blockIdx.y, db = blockIdx.x;
    const float* Ain = Skk + (long)z * CHK * CHK;
    float* T = Ti + (long)z * CHK * CHK;
    __shared__ float A[64][64];
    __shared__ float Ts[64][64];
    int j = threadIdx.x;
    int off = db * 64;
    for (int t = 0; t < 64; t++) A[t][j] = Ain[(long)(off + t) * CHK + off + j] + 1.0f;
    __syncthreads();
    for (int t = 0; t < 64; t++) {
        float v;
        if (t < j) v = 0.f;
        else if (t == j) v = 1.f;
        else {
            float ss = 0.f;
            for (int i = j; i < t; i++) ss += A[t][i] * Ts[i][j];
            v = -LAM * ss;
        }
        Ts[t][j] = v;
    }
    __syncthreads();
    for (int t = 0; t < 64; t++) T[(long)(off + t) * CHK + off + j] = Ts[t][j];
    if (db == 0)
        for (int t = 0; t < 64; t++) T[(long)t * CHK + 64 + j] = 0.f;
}

__global__ void __launch_bounds__(256) tcomb_kernel(
    const float* __restrict__ Skk, float* __restrict__ Ti)
{
    long z = blockIdx.x;
    const float* Sk = Skk + z * CHK * CHK;
    float* T = Ti + z * CHK * CHK;
    __shared__ float T11[64 * 64];
    __shared__ float T22[64 * 64];
    __shared__ float X  [64 * 64];
    int tid = threadIdx.x;
    for (int i = tid; i < 4096; i += 256) {
        int r = i >> 6, c = i & 63;
        T11[i] = T[(long)r * CHK + c];
        T22[i] = T[(long)(64 + r) * CHK + 64 + c];
    }
    __syncthreads();
    int t = tid >> 2, jg = (tid & 3) << 4;
    float xr[16];
#pragma unroll
    for (int j = 0; j < 16; j++) xr[j] = 0.f;
    for (int i = 0; i < 64; i++) {
        float l = LAM * (Sk[(long)(64 + t) * CHK + i] + 1.0f);
#pragma unroll
        for (int j = 0; j < 16; j++) xr[j] += l * T11[(i << 6) + jg + j];
    }
#pragma unroll
    for (int j = 0; j < 16; j++) X[(t << 6) + jg + j] = xr[j];
    __syncthreads();
    float yr[16];
#pragma unroll
    for (int j = 0; j < 16; j++) yr[j] = 0.f;
    for (int i = 0; i < 64; i++) {
        float l = T22[(t << 6) + i];
#pragma unroll
        for (int j = 0; j < 16; j++) yr[j] += l * X[(i << 6) + jg + j];
    }
#pragma unroll
    for (int j = 0; j < 16; j++) T[(long)(64 + t) * CHK + jg + j] = -yr[j];
}

// =====================================================================
// Solve: G = Ti @ Up  (128x1024, K=128) — SIMT f32x2
// =====================================================================
__global__ void __launch_bounds__(256) solve_kernel(int chunk,
    const float* __restrict__ Ti, const float* __restrict__ Up, float* __restrict__ G)
{
    int b = blockIdx.z, rt = blockIdx.y, n0 = blockIdx.x << 7;
    const float* T = Ti + ((long)b * NCHK + chunk) * CHK * CHK + (long)rt * 64 * CHK;
    const float* B = Up + (long)b * CHK * DD;
    float* Gb = G + (long)b * CHK * DD + (long)rt * 64 * DD;
    __shared__ float SA[16][68];
    __shared__ float SB[16][132];
    int tid = threadIdx.x, tx = tid & 15, ty = tid >> 4;
    int ar = tid >> 2, ac = (tid & 3) << 2;
    int kr = tid >> 5, bc = (tid & 31) << 2;
    ull acc[4][4] = {};
    for (int kb = 0; kb < CHK; kb += 16) {
        float4 a0 = *(const float4*)(T + (long)ar * CHK + kb + ac);
        float4 b0 = *(const float4*)(B + (long)(kb + kr) * DD + n0 + bc);
        float4 b1 = *(const float4*)(B + (long)(kb + kr + 8) * DD + n0 + bc);
        __syncthreads();
        SA[ac+0][ar]=a0.x; SA[ac+1][ar]=a0.y; SA[ac+2][ar]=a0.z; SA[ac+3][ar]=a0.w;
        *(float4*)&SB[kr][bc] = b0;
        *(float4*)&SB[kr + 8][bc] = b1;
        __syncthreads();
#pragma unroll
        for (int kk = 0; kk < 16; kk++) {
            float4 av = *(const float4*)&SA[kk][ty << 2];
            F4U B0, B1;
            B0.f = *(const float4*)&SB[kk][tx << 2];
            B1.f = *(const float4*)&SB[kk][64 + (tx << 2)];
            mm4x8(acc, av, B0, B1);
        }
    }
    int c0 = n0 + (tx << 2), c1 = c0 + 64;
#pragma unroll
    for (int i = 0; i < 4; i++) {
        long row = (ty << 2) + i;
        float2 p0 = unp(acc[i][0]), p1 = unp(acc[i][1]), p2 = unp(acc[i][2]), p3 = unp(acc[i][3]);
        *(float4*)(Gb + row * DD + c0) = make_float4(p0.x, p0.y, p1.x, p1.y);
        *(float4*)(Gb + row * DD + c1) = make_float4(p2.x, p2.y, p3.x, p3.y);
    }
}

// =====================================================================
// Z2a: out_c -= LR * (masked(Aqk+1)) @ G   (128x1024, K=128) — SIMT
// =====================================================================
__global__ void __launch_bounds__(256) z2a_kernel(int chunk,
    const float* __restrict__ Aqk, const float* __restrict__ G, float* __restrict__ out)
{
    int b = blockIdx.z, rt = blockIdx.y, n0 = blockIdx.x << 7;
    const float* Aq = Aqk + ((long)b * NCHK + chunk) * CHK * CHK;
    const float* B = G + (long)b * CHK * DD;
    float* O = out + ((long)b * SS + (long)chunk * CHK + rt * 64) * DD;
    __shared__ float SA[16][68];
    __shared__ float SB[16][132];
    int tid = threadIdx.x, tx = tid & 15, ty = tid >> 4;
    int ar = tid >> 2, ac = (tid & 3) << 2;
    int kr = tid >> 5, bc = (tid & 31) << 2;
    int tglob = rt * 64 + ar;
    ull acc[4][4] = {};
    for (int kb = 0; kb < CHK; kb += 16) {
        float4 a0 = *(const float4*)(Aq + (long)tglob * CHK + kb + ac);
        float4 b0 = *(const float4*)(B + (long)(kb + kr) * DD + n0 + bc);
        float4 b1 = *(const float4*)(B + (long)(kb + kr + 8) * DD + n0 + bc);
        __syncthreads();
        int i0 = kb + ac;
        SA[ac+0][ar] = (i0+0 <= tglob) ? a0.x + 1.0f : 0.f;
        SA[ac+1][ar] = (i0+1 <= tglob) ? a0.y + 1.0f : 0.f;
        SA[ac+2][ar] = (i0+2 <= tglob) ? a0.z + 1.0f : 0.f;
        SA[ac+3][ar] = (i0+3 <= tglob) ? a0.w + 1.0f : 0.f;
        *(float4*)&SB[kr][bc] = b0;
        *(float4*)&SB[kr + 8][bc] = b1;
        __syncthreads();
#pragma unroll
        for (int kk = 0; kk < 16; kk++) {
            float4 av = *(const float4*)&SA[kk][ty << 2];
            F4U B0, B1;
            B0.f = *(const float4*)&SB[kk][tx << 2];
            B1.f = *(const float4*)&SB[kk][64 + (tx << 2)];
            mm4x8(acc, av, B0, B1);
        }
    }
    int c0 = n0 + (tx << 2), c1 = c0 + 64;
#pragma unroll
    for (int i = 0; i < 4; i++) {
        long row = (ty << 2) + i;
        float2 p0 = unp(acc[i][0]), p1 = unp(acc[i][1]), p2 = unp(acc[i][2]), p3 = unp(acc[i][3]);
        float4 o0 = *(const float4*)(O + row * DD + c0);
        float4 o1 = *(const float4*)(O + row * DD + c1);
        o0.x -= LRc * p0.x; o0.y -= LRc * p0.y; o0.z -= LRc * p1.x; o0.w -= LRc * p1.y;
        o1.x -= LRc * p2.x; o1.y -= LRc * p2.y; o1.z -= LRc * p3.x; o1.w -= LRc * p3.y;
        *(float4*)(O + row * DD + c0) = o0;
        *(float4*)(O + row * DD + c1) = o1;
    }
}

__global__ void zero_kernel(float* __restrict__ p, long n)
{
    long i = (long)blockIdx.x * blockDim.x + threadIdx.x;
    long stride = (long)gridDim.x * blockDim.x;
    for (; i < n; i += stride) p[i] = 0.f;
}

// =====================================================================
// host launcher
// =====================================================================
extern "C" void kernel_launch(void* const* d_in, const int* in_sizes, int n_in,
                              void* d_out, int out_size)
{
    (void)in_sizes; (void)n_in; (void)out_size;
    const float* in_seq = (const float*)d_in[0];
    const float* thK = (const float*)d_in[1];
    const float* thV = (const float*)d_in[2];
    const float* thQ = (const float*)d_in[3];
    const float* W0  = (const float*)d_in[4];
    const float* b0  = (const float*)d_in[5];
    float* out = (float*)d_out;

    float *pK, *pQ, *pU, *ps, *pG, *pUp, *pSkk, *pAqk, *pTi, *pE, *pF;
    bf16 *pX2, *pWK, *pWQ, *pWE, *pWF, *pK2a, *pQ2a, *pK2b, *pKt2, *pM2, *pGt2;
    cudaGetSymbolAddress((void**)&pK, g_K);
    cudaGetSymbolAddress((void**)&pQ, g_Q);
    cudaGetSymbolAddress((void**)&pU, g_U);
    cudaGetSymbolAddress((void**)&ps, g_s);
    cudaGetSymbolAddress((void**)&pG, g_G);
    cudaGetSymbolAddress((void**)&pUp, g_Up);
    cudaGetSymbolAddress((void**)&pSkk, g_Skk);
    cudaGetSymbolAddress((void**)&pAqk, g_Aqk);
    cudaGetSymbolAddress((void**)&pTi, g_Ti);
    cudaGetSymbolAddress((void**)&pE, g_E);
    cudaGetSymbolAddress((void**)&pF, g_F);
    cudaGetSymbolAddress((void**)&pX2, g_X2);
    cudaGetSymbolAddress((void**)&pWK, g_WK);
    cudaGetSymbolAddress((void**)&pWQ, g_WQ);
    cudaGetSymbolAddress((void**)&pWE, g_WE);
    cudaGetSymbolAddress((void**)&pWF, g_WF);
    cudaGetSymbolAddress((void**)&pK2a, g_K2a);
    cudaGetSymbolAddress((void**)&pQ2a, g_Q2a);
    cudaGetSymbolAddress((void**)&pK2b, g_K2b);
    cudaGetSymbolAddress((void**)&pKt2, g_Kt2);
    cudaGetSymbolAddress((void**)&pM2, g_M2);
    cudaGetSymbolAddress((void**)&pGt2, g_Gt2);

    // E = W0@thK - thV, F = W0@thQ (fp32)
    dim3 g16(16, 16, 1);
    gemm_nn<<<g16, 256>>>(W0, DD, thK, DD, pE, DD, thV, -1.f, 1.f, DD);
    gemm_nn<<<g16, 256>>>(W0, DD, thQ, DD, pF, DD, nullptr, 0.f, 1.f, DD);

    // split-bf16 conversions for projections
    cvt_a_kernel<<<8192, 256>>>(in_seq, pX2, (long)BB * SS * DD);
    cvt_b_kernel<<<1024, 256>>>(thK, pWK, (long)DD * DD);
    cvt_b_kernel<<<1024, 256>>>(thQ, pWQ, (long)DD * DD);
    cvt_b_kernel<<<1024, 256>>>(pE,  pWE, (long)DD * DD);
    cvt_b_kernel<<<1024, 256>>>(pF,  pWF, (long)DD * DD);

    // big projections via HMMA
    dim3 gm(DD / 128, (BB * SS) / 128, 1);
    hmma_proj<<<gm, 256>>>(pX2, pWK, pK, nullptr, 1.f);
    hmma_proj<<<gm, 256>>>(pX2, pWQ, pQ, nullptr, 1.f);
    hmma_proj<<<gm, 256>>>(pX2, pWE, pU, b0, GSC);
    hmma_proj<<<gm, 256>>>(pX2, pWF, out, b0, 1.f);

    // split conversions of K/Q for chunk-loop HMMA
    cvt_a_kernel<<<8192, 256>>>(pK, pK2a, (long)BB * SS * DD);
    cvt_a_kernel<<<8192, 256>>>(pQ, pQ2a, (long)BB * SS * DD);
    cvt_b_kernel<<<8192, 256>>>(pK, pK2b, (long)BB * SS * DD);
    kt_kernel<<<dim3(32, BB * NCHK), 256>>>(pK, pKt2);

    // Gram matrices + triangular inverses
    hmma_pair<<<dim3(2, BB * NCHK), 256>>>(pK2a, pQ2a, pK2b, pSkk, pAqk);
    tinv64_kernel<<<dim3(2, BB * NCHK), 64>>>(pSkk, pTi);
    tcomb_kernel<<<BB * NCHK, 256>>>(pSkk, pTi);

    // zero state
    zero_kernel<<<2048, 256>>>((float*)pM2, (long)BB * DD * K3 / 2);
    zero_kernel<<<8, 256>>>(ps, (long)BB * DD);

    // chunk loop
    for (int c = 0; c < NCHK; c++) {
        hmma_cross<<<dim3(8, 2, BB), 256>>>(c, pK2a, pQ2a, pM2, pU, ps, pUp, out);
        solve_kernel<<<dim3(8, 2, BB), 256>>>(c, pTi, pUp, pG);
        z2a_kernel<<<dim3(8, 2, BB), 256>>>(c, pAqk, pG, out);
        if (c + 1 < NCHK) {
            colsum_kernel<<<dim3(4, BB), 256>>>(pG, ps);
            gt_kernel<<<dim3(32, BB), 256>>>(pG, pGt2);
            hmma_z2b<<<dim3(8, 8, BB), 256>>>(c, pGt2, pKt2, pM2);
        }
    }
}